// round 12
// baseline (speedup 1.0000x reference)
#include <cuda_runtime.h>
#include <cuda_fp16.h>
#include <cstdint>

// Problem constants
#define BB 2
#define CC 256
#define HH 64
#define WW 64
#define HWC (HH*WW)          // 4096
#define NQ (BB*HWC)          // 8192
#define NLVL 4
#define RAD 4
#define QT 16                // queries per tile
#define WS 112               // per-query w0 stride (100 used, padded)

// GEMM tiling: 128x128 block tile, 8 warps of 32x64, K chunks of 64, 3 stages
#define TM 128
#define TN 128
#define KC 64
#define NSTAGE 3
#define STAGE_BYTES ((TM+TN)*KC*2)           // 32 KB per stage
#define GEMM_SMEM_BYTES (NSTAGE*STAGE_BYTES + 1024)

// Merged pool+sample smem layout (dynamic)
#define SMP_SL1 0                            // __half [16][1024]  32 KB
#define SMP_SL2 32768                        // float  [16][256]   16 KB
#define SMP_SL3 49152                        // float  [16][64]     4 KB
#define SMP_SW  53248                        // float  [16][400]   25.6 KB
#define SAMPLE_SMEM_BYTES 78848

// Scratch (device globals; allocation-free rule)
__device__ __half g_f1h[BB*HWC*CC];          // (B, HW, C) fp16, 4 MB
__device__ __half g_f2h[BB*HWC*CC];          // (B, HW, C) fp16, 4 MB
__device__ __half g_f2l1[BB*1024*CC];        // pooled f2 (l1), 1 MB
__device__ __half g_c1[(size_t)NQ*32*32];    // corr lvl1 volume, 16.8 MB
__device__ __half g_w0[(size_t)NQ*WS];       // per-query l0 10x10 windows

__device__ __forceinline__ uint32_t smem_u32(const void* p) {
    uint32_t a;
    asm("{ .reg .u64 t; cvta.to.shared.u64 t, %1; cvt.u32.u64 %0, t; }"
        : "=r"(a) : "l"(p));
    return a;
}
__device__ __forceinline__ void cp16(uint32_t dst, const void* gsrc) {
    asm volatile("cp.async.cg.shared.global [%0], [%1], 16;"
                 :: "r"(dst), "l"(__cvta_generic_to_global(gsrc)) : "memory");
}
__device__ __forceinline__ void cp_commit() {
    asm volatile("cp.async.commit_group;" ::: "memory");
}
template <int N>
__device__ __forceinline__ void cp_wait() {
    asm volatile("cp.async.wait_group %0;" :: "n"(N) : "memory");
}

// ---------------------------------------------------------------------------
// Transpose both fmaps: (B,C,HW) fp32 -> (B,HW,C) fp16, one launch
// ---------------------------------------------------------------------------
__global__ void transpose_both_kernel(const float* __restrict__ in1,
                                      const float* __restrict__ in2) {
    __shared__ float tile[32][33];
    int z   = blockIdx.z;                // 0..2*BB-1
    int b   = z & (BB - 1);
    const float* in = (z < BB) ? in1 : in2;
    __half* outp    = (z < BB) ? g_f1h : g_f2h;
    int hw0 = blockIdx.x*32, c0 = blockIdx.y*32;
    int tx = threadIdx.x, ty = threadIdx.y;
#pragma unroll
    for (int i = 0; i < 32; i += 8)
        tile[ty + i][tx] = in[(b*CC + c0 + ty + i) * HWC + hw0 + tx];
    __syncthreads();
#pragma unroll
    for (int i = 0; i < 32; i += 8)
        outp[((size_t)b*HWC + hw0 + ty + i) * CC + c0 + tx] =
            __float2half_rn(tile[tx][ty + i]);
}

// ---------------------------------------------------------------------------
// Pool f2 features to level-1 grid: f2l1[b, y1*32+x1, c] = mean of 2x2 f2
// ---------------------------------------------------------------------------
__global__ void pool_f2_kernel() {
    int idx = blockIdx.x * blockDim.x + threadIdx.x;
    if (idx >= BB * 1024 * (CC/2)) return;
    int c2 = idx & 127;
    int j  = (idx >> 7) & 1023;
    int b  = idx >> 17;
    int y1 = j >> 5, x1 = j & 31;
    const __half2* base = (const __half2*)g_f2h + (size_t)b * HWC * (CC/2);
    float2 a  = __half22float2(base[((2*y1  )*64 + 2*x1  ) * 128 + c2]);
    float2 bb = __half22float2(base[((2*y1  )*64 + 2*x1+1) * 128 + c2]);
    float2 c  = __half22float2(base[((2*y1+1)*64 + 2*x1  ) * 128 + c2]);
    float2 d  = __half22float2(base[((2*y1+1)*64 + 2*x1+1) * 128 + c2]);
    ((__half2*)g_f2l1)[idx] =
        __floats2half2_rn(0.25f * (a.x + bb.x + c.x + d.x),
                          0.25f * (a.y + bb.y + c.y + d.y));
}

// ---------------------------------------------------------------------------
// Pipelined GEMM (mma.sync, 32x64 warp tiles, 3-stage cp.async):
// c1[b, i, j1] = <f1[i], f2l1[j1]> / 16, M=4096, N=1024, K=256.
// ---------------------------------------------------------------------------
__global__ __launch_bounds__(256, 2)
void gemm_l1_kernel() {
    extern __shared__ __align__(16) char dsm[];
    uint32_t raw = smem_u32(dsm);
    uint32_t sb  = (raw + 1023u) & ~1023u;
    char*    smp = dsm + (sb - raw);

    int tid = threadIdx.x;
    int lid = tid & 31;
    int w   = tid >> 5;
    int wm  = w & 3;                          // M group (4 x 32)
    int wn  = w >> 2;                         // N group (2 x 64)
    int b   = blockIdx.z;
    int i0  = blockIdx.y * TM;
    int j0  = blockIdx.x * TN;

    const uint4* gA = (const uint4*)(g_f1h  + ((size_t)(b*HWC  + i0)) * CC);
    const uint4* gB = (const uint4*)(g_f2l1 + ((size_t)(b*1024 + j0)) * CC);

    auto load_stage = [&](int st, int kc) {
        uint32_t sS = sb + st * STAGE_BYTES;
#pragma unroll
        for (int i = 0; i < 4; i++) {
            int idx = tid + i * 256;
            int r = idx >> 3, cl = idx & 7;
            uint32_t off = (uint32_t)r * 128u + (uint32_t)((cl ^ (r & 7)) << 4);
            cp16(sS + off, gA + r * 32 + kc * 8 + cl);
        }
#pragma unroll
        for (int i = 0; i < 4; i++) {
            int idx = tid + i * 256;
            int r = idx >> 3, cl = idx & 7;
            uint32_t off = (uint32_t)r * 128u + (uint32_t)((cl ^ (r & 7)) << 4);
            cp16(sS + TM*KC*2 + off, gB + r * 32 + kc * 8 + cl);
        }
        cp_commit();
    };

    float acc[2][8][4];
#pragma unroll
    for (int mi = 0; mi < 2; mi++)
#pragma unroll
        for (int j = 0; j < 8; j++)
#pragma unroll
            for (int u = 0; u < 4; u++) acc[mi][j][u] = 0.f;

    int m0 = wm * 32;
    int nb = wn * 64;
    int arow = m0 + (lid & 15);
    int acb  = lid >> 4;
    int brow = nb + (lid & 7) + ((lid >> 4) << 3);
    int bcb  = (lid >> 3) & 1;

    load_stage(0, 0);
    load_stage(1, 1);

#pragma unroll
    for (int kc = 0; kc < 4; kc++) {
        if (kc < 3) cp_wait<1>(); else cp_wait<0>();
        __syncthreads();
        if (kc < 2) load_stage((kc + 2) % NSTAGE, kc + 2);

        uint32_t sA = sb + (kc % NSTAGE) * STAGE_BYTES;
        uint32_t sB = sA + TM*KC*2;
#pragma unroll
        for (int ks = 0; ks < 4; ks++) {
            uint32_t a[2][4];
#pragma unroll
            for (int mi = 0; mi < 2; mi++) {
                int row = arow + mi * 16;
                int ch  = ks * 2 + acb;
                uint32_t addr = sA + (uint32_t)row * 128u
                              + (uint32_t)((ch ^ (row & 7)) << 4);
                asm volatile(
                    "ldmatrix.sync.aligned.m8n8.x4.shared.b16 {%0,%1,%2,%3}, [%4];"
                    : "=r"(a[mi][0]), "=r"(a[mi][1]), "=r"(a[mi][2]), "=r"(a[mi][3])
                    : "r"(addr));
            }
            uint32_t bf[4][4];
#pragma unroll
            for (int ng = 0; ng < 4; ng++) {
                int row = brow + ng * 16;
                int ch  = ks * 2 + bcb;
                uint32_t addr = sB + (uint32_t)row * 128u
                              + (uint32_t)((ch ^ (row & 7)) << 4);
                asm volatile(
                    "ldmatrix.sync.aligned.m8n8.x4.shared.b16 {%0,%1,%2,%3}, [%4];"
                    : "=r"(bf[ng][0]), "=r"(bf[ng][1]), "=r"(bf[ng][2]), "=r"(bf[ng][3])
                    : "r"(addr));
            }
#pragma unroll
            for (int mi = 0; mi < 2; mi++)
#pragma unroll
                for (int j = 0; j < 8; j++) {
                    int ng = j >> 1, pr = (j & 1) * 2;
                    asm volatile(
                        "mma.sync.aligned.m16n8k16.row.col.f32.f16.f16.f32 "
                        "{%0,%1,%2,%3}, {%4,%5,%6,%7}, {%8,%9}, {%0,%1,%2,%3};"
                        : "+f"(acc[mi][j][0]), "+f"(acc[mi][j][1]),
                          "+f"(acc[mi][j][2]), "+f"(acc[mi][j][3])
                        : "r"(a[mi][0]), "r"(a[mi][1]), "r"(a[mi][2]), "r"(a[mi][3]),
                          "r"(bf[ng][pr]), "r"(bf[ng][pr + 1]));
                }
        }
        __syncthreads();
    }

    // ---- epilogue: fragments -> smem tile (128x128 fp16) -> c1 ----
    {
        __half* epi = (__half*)smp;           // 32 KB, reuse stage 0
        const float s = 0.0625f;              // 1/sqrt(256)
#pragma unroll
        for (int mi = 0; mi < 2; mi++)
#pragma unroll
            for (int j = 0; j < 8; j++) {
                int n = nb + j * 8 + (lid & 3) * 2;
                int m = m0 + mi * 16 + (lid >> 2);
                *(__half2*)(epi + m * 128 + n) =
                    __floats2half2_rn(acc[mi][j][0] * s, acc[mi][j][1] * s);
                *(__half2*)(epi + (m + 8) * 128 + n) =
                    __floats2half2_rn(acc[mi][j][2] * s, acc[mi][j][3] * s);
            }
        __syncthreads();
        const uint4* ev = (const uint4*)epi;
#pragma unroll
        for (int it = 0; it < 8; it++) {
            int idx = tid + it * 256;         // 2048 uint4
            int r = idx >> 4, c = idx & 15;
            *(uint4*)(g_c1 + ((size_t)(b*HWC + i0 + r)) * 1024 + j0 + c * 8) =
                ev[idx];
        }
    }
}

// ---------------------------------------------------------------------------
// Direct level-0 window dots: w0[q][t] = <f1_q, f2[tap_t]> / 16 (0 if OOB).
// Block = 16 queries; 32 groups of 8 lanes; lane owns 32 channels.
// ---------------------------------------------------------------------------
__global__ __launch_bounds__(256)
void w0_sample_kernel(const float* __restrict__ coords) {
    int bidx = blockIdx.x;
    int b    = bidx >> 8;
    int hw0  = (bidx & 255) * QT;
    int tid  = threadIdx.x;
    int sub  = tid & 7;
    int grp  = tid >> 3;
    int q    = grp >> 1;
    int half = grp & 1;
    int n    = b * HWC + hw0 + q;

    float rf1[32];
    {
        const uint4* p = (const uint4*)(g_f1h + (size_t)n * CC + sub * 32);
#pragma unroll
        for (int u = 0; u < 4; u++) {
            uint4 h8 = p[u];
            float2 f;
            f = __half22float2(*(const __half2*)&h8.x);
            rf1[u*8+0] = f.x; rf1[u*8+1] = f.y;
            f = __half22float2(*(const __half2*)&h8.y);
            rf1[u*8+2] = f.x; rf1[u*8+3] = f.y;
            f = __half22float2(*(const __half2*)&h8.z);
            rf1[u*8+4] = f.x; rf1[u*8+5] = f.y;
            f = __half22float2(*(const __half2*)&h8.w);
            rf1[u*8+6] = f.x; rf1[u*8+7] = f.y;
        }
    }
    float xq = coords[(b*2 + 0) * HWC + hw0 + q];
    float yq = coords[(b*2 + 1) * HWC + hw0 + q];
    int bx = (int)floorf(xq) - RAD;
    int by = (int)floorf(yq) - RAD;
    const __half* f2b = g_f2h + (size_t)b * HWC * CC;

#pragma unroll 5
    for (int t = half; t < 100; t += 2) {
        int ty = (t * 205) >> 11;            // /10
        int tx = t - ty * 10;
        int ix = bx + tx, iy = by + ty;
        float acc0 = 0.f, acc1 = 0.f;
        if (((unsigned)ix < 64u) & ((unsigned)iy < 64u)) {
            const uint4* p =
                (const uint4*)(f2b + ((size_t)(iy*64 + ix)) * CC + sub * 32);
            uint4 h0 = p[0], h1 = p[1], h2 = p[2], h3 = p[3];
            float2 f;
            f = __half22float2(*(const __half2*)&h0.x);
            acc0 = fmaf(rf1[ 0], f.x, acc0); acc0 = fmaf(rf1[ 1], f.y, acc0);
            f = __half22float2(*(const __half2*)&h0.y);
            acc0 = fmaf(rf1[ 2], f.x, acc0); acc0 = fmaf(rf1[ 3], f.y, acc0);
            f = __half22float2(*(const __half2*)&h0.z);
            acc0 = fmaf(rf1[ 4], f.x, acc0); acc0 = fmaf(rf1[ 5], f.y, acc0);
            f = __half22float2(*(const __half2*)&h0.w);
            acc0 = fmaf(rf1[ 6], f.x, acc0); acc0 = fmaf(rf1[ 7], f.y, acc0);
            f = __half22float2(*(const __half2*)&h1.x);
            acc1 = fmaf(rf1[ 8], f.x, acc1); acc1 = fmaf(rf1[ 9], f.y, acc1);
            f = __half22float2(*(const __half2*)&h1.y);
            acc1 = fmaf(rf1[10], f.x, acc1); acc1 = fmaf(rf1[11], f.y, acc1);
            f = __half22float2(*(const __half2*)&h1.z);
            acc1 = fmaf(rf1[12], f.x, acc1); acc1 = fmaf(rf1[13], f.y, acc1);
            f = __half22float2(*(const __half2*)&h1.w);
            acc1 = fmaf(rf1[14], f.x, acc1); acc1 = fmaf(rf1[15], f.y, acc1);
            f = __half22float2(*(const __half2*)&h2.x);
            acc0 = fmaf(rf1[16], f.x, acc0); acc0 = fmaf(rf1[17], f.y, acc0);
            f = __half22float2(*(const __half2*)&h2.y);
            acc0 = fmaf(rf1[18], f.x, acc0); acc0 = fmaf(rf1[19], f.y, acc0);
            f = __half22float2(*(const __half2*)&h2.z);
            acc0 = fmaf(rf1[20], f.x, acc0); acc0 = fmaf(rf1[21], f.y, acc0);
            f = __half22float2(*(const __half2*)&h2.w);
            acc0 = fmaf(rf1[22], f.x, acc0); acc0 = fmaf(rf1[23], f.y, acc0);
            f = __half22float2(*(const __half2*)&h3.x);
            acc1 = fmaf(rf1[24], f.x, acc1); acc1 = fmaf(rf1[25], f.y, acc1);
            f = __half22float2(*(const __half2*)&h3.y);
            acc1 = fmaf(rf1[26], f.x, acc1); acc1 = fmaf(rf1[27], f.y, acc1);
            f = __half22float2(*(const __half2*)&h3.z);
            acc1 = fmaf(rf1[28], f.x, acc1); acc1 = fmaf(rf1[29], f.y, acc1);
            f = __half22float2(*(const __half2*)&h3.w);
            acc1 = fmaf(rf1[30], f.x, acc1); acc1 = fmaf(rf1[31], f.y, acc1);
        }
        float acc = acc0 + acc1;
        acc += __shfl_down_sync(0xffffffffu, acc, 4);
        acc += __shfl_down_sync(0xffffffffu, acc, 2);
        acc += __shfl_down_sync(0xffffffffu, acc, 1);
        if (sub == 0)
            g_w0[(size_t)n * WS + t] = __float2half_rn(acc * 0.0625f);
    }
}

// ---------------------------------------------------------------------------
// Merged pool+sample: block = 16 queries. l1 rows -> smem; l2/l3 pooled in
// smem (fp32); windows staged; 324 bilinear outputs/query. No divisions.
// ---------------------------------------------------------------------------
__global__ __launch_bounds__(256)
void pool_sample_kernel(const float* __restrict__ coords,
                        float* __restrict__ out) {
    extern __shared__ __align__(16) char sm[];
    __half* sl1 = (__half*)(sm + SMP_SL1);     // [16][1024]
    float*  sl2 = (float*) (sm + SMP_SL2);     // [16][256]
    float*  sl3 = (float*) (sm + SMP_SL3);     // [16][64]
    float*  sW  = (float*) (sm + SMP_SW);      // [16][400]
    __shared__ float sX[QT], sY[QT];

    int bidx = blockIdx.x;                     // 0..511
    int b    = bidx >> 8;
    int hw0  = (bidx & 255) * QT;
    int n0   = b * HWC + hw0;
    int tid  = threadIdx.x;

    if (tid < QT) {
        sX[tid] = coords[(b*2 + 0) * HWC + hw0 + tid];
        sY[tid] = coords[(b*2 + 1) * HWC + hw0 + tid];
    }

    // load 16 l1 rows (contiguous 32 KB)
    {
        const uint4* src = (const uint4*)(g_c1 + (size_t)n0 * 1024);
        uint4* dst = (uint4*)sl1;
#pragma unroll
        for (int i = 0; i < 8; i++) dst[tid + i*256] = src[tid + i*256];
    }
    __syncthreads();

    // l2 pool (fp32): 4096 cells
#pragma unroll
    for (int i = 0; i < 16; i++) {
        int c = tid + i*256;
        int q = c >> 8, r = c & 255;
        int y = r >> 4, x = r & 15;
        const __half* base = sl1 + q*1024 + (2*y)*32 + 2*x;
        float2 p0 = __half22float2(*(const __half2*)base);
        float2 p1 = __half22float2(*(const __half2*)(base + 32));
        sl2[c] = 0.25f * (p0.x + p0.y + p1.x + p1.y);
    }
    __syncthreads();

    // l3 pool: 1024 cells
#pragma unroll
    for (int i = 0; i < 4; i++) {
        int c = tid + i*256;
        int q = c >> 6, r = c & 63;
        int y = r >> 3, x = r & 7;
        const float* base = sl2 + q*256 + (2*y)*16 + 2*x;
        sl3[c] = 0.25f * (base[0] + base[1] + base[16] + base[17]);
    }
    __syncthreads();

    // stage windows: per level, 1600 = 16 q x 100 taps
#pragma unroll
    for (int l = 0; l < 4; l++) {
#pragma unroll
        for (int i = 0; i < 7; i++) {
            int idx = tid + i*256;
            if (idx < 1600) {
                int q  = (int)(((unsigned)idx * 5243u) >> 19);   // /100
                int t  = idx - q * 100;
                int ty = (int)(((unsigned)t * 205u) >> 11);      // /10
                int tx = t - ty * 10;
                float sc = 1.0f / (float)(1 << l);
                float xc = sX[q] * sc, yc = sY[q] * sc;
                int ix = (int)floorf(xc) - RAD + tx;
                int iy = (int)floorf(yc) - RAD + ty;
                int Wl = 64 >> l;
                float v = 0.f;
                if (ix >= 0 && ix < Wl && iy >= 0 && iy < Wl) {
                    if      (l == 0) v = __half2float(g_w0[(size_t)(n0+q)*WS + t]);
                    else if (l == 1) v = __half2float(sl1[q*1024 + iy*32 + ix]);
                    else if (l == 2) v = sl2[q*256 + iy*16 + ix];
                    else             v = sl3[q*64 + iy*8 + ix];
                }
                sW[q*400 + l*100 + t] = v;
            }
        }
    }
    __syncthreads();

    // outputs: per level, 1296 = 81 taps x 16 q
#pragma unroll
    for (int l = 0; l < 4; l++) {
        float sc = 1.0f / (float)(1 << l);
#pragma unroll
        for (int i = 0; i < 6; i++) {
            int idx = tid + i*256;
            if (idx < 1296) {
                int k  = idx >> 4;
                int qq = idx & 15;
                int cx = (int)(((unsigned)k * 57u) >> 9);        // /9
                int ry = k - cx * 9;
                float xq = sX[qq] * sc;
                float yq = sY[qq] * sc;
                float fx = xq - floorf(xq);
                float fy = yq - floorf(yq);
                const float* W = sW + qq*400 + l*100;
                float v00 = W[ ry      * 10 + cx    ];
                float v01 = W[ ry      * 10 + cx + 1];
                float v10 = W[(ry + 1) * 10 + cx    ];
                float v11 = W[(ry + 1) * 10 + cx + 1];
                float v = (1.f - fy) * ((1.f - fx) * v00 + fx * v01)
                        +        fy  * ((1.f - fx) * v10 + fx * v11);
                out[((size_t)(b * 324 + l * 81 + k)) * HWC + hw0 + qq] = v;
            }
        }
    }
}

// ---------------------------------------------------------------------------
extern "C" void kernel_launch(void* const* d_in, const int* in_sizes, int n_in,
                              void* d_out, int out_size) {
    const float* fmap1  = (const float*)d_in[0];
    const float* fmap2  = (const float*)d_in[1];
    const float* coords = (const float*)d_in[2];
    float* out = (float*)d_out;

    cudaFuncSetAttribute(gemm_l1_kernel,
                         cudaFuncAttributeMaxDynamicSharedMemorySize,
                         GEMM_SMEM_BYTES);
    cudaFuncSetAttribute(pool_sample_kernel,
                         cudaFuncAttributeMaxDynamicSharedMemorySize,
                         SAMPLE_SMEM_BYTES);

    dim3 tgrid(HWC / 32, CC / 32, 2*BB);
    dim3 tblk(32, 8);
    transpose_both_kernel<<<tgrid, tblk>>>(fmap1, fmap2);

    pool_f2_kernel<<<(BB*1024*(CC/2) + 255) / 256, 256>>>();

    dim3 ggrid(1024 / TN, HWC / TM, BB);  // (8, 32, 2)
    gemm_l1_kernel<<<ggrid, 256, GEMM_SMEM_BYTES>>>();

    w0_sample_kernel<<<NQ / QT, 256>>>(coords);

    pool_sample_kernel<<<NQ / QT, 256, SAMPLE_SMEM_BYTES>>>(coords, out);
}

// round 13
// speedup vs baseline: 1.0196x; 1.0196x over previous
#include <cuda_runtime.h>
#include <cuda_fp16.h>
#include <cstdint>

// Problem constants
#define BB 2
#define CC 256
#define HH 64
#define WW 64
#define HWC (HH*WW)          // 4096
#define NQ (BB*HWC)          // 8192
#define NLVL 4
#define RAD 4
#define QT 16                // queries per tile
#define WS 112               // per-query w0 stride (100 used, padded)

// GEMM tiling: 128x128 block tile, 8 warps of 32x64, K chunks of 64, 3 stages
#define TM 128
#define TN 128
#define KC 64
#define NSTAGE 3
#define STAGE_BYTES ((TM+TN)*KC*2)           // 32 KB per stage
#define GEMM_SMEM_BYTES (NSTAGE*STAGE_BYTES + 1024)

// Merged pool+sample smem layout (dynamic)
#define SMP_SL1 0                            // __half [16][1024]  32 KB
#define SMP_SL2 32768                        // float  [16][256]   16 KB
#define SMP_SL3 49152                        // float  [16][64]     4 KB
#define SMP_SW  53248                        // float  [16][400]   25.6 KB
#define SAMPLE_SMEM_BYTES 78848

// Scratch (device globals; allocation-free rule)
__device__ __half g_f1h[BB*HWC*CC];          // (B, HW, C) fp16, 4 MB
__device__ __half g_f2h[BB*HWC*CC];          // (B, HW, C) fp16, 4 MB
__device__ __half g_f2l1[BB*1024*CC];        // pooled f2 (l1), 1 MB
__device__ __half g_c1[(size_t)NQ*32*32];    // corr lvl1 volume, 16.8 MB
__device__ __half g_w0[(size_t)NQ*WS];       // per-query l0 10x10 windows

__device__ __forceinline__ uint32_t smem_u32(const void* p) {
    uint32_t a;
    asm("{ .reg .u64 t; cvta.to.shared.u64 t, %1; cvt.u32.u64 %0, t; }"
        : "=r"(a) : "l"(p));
    return a;
}
__device__ __forceinline__ void cp16(uint32_t dst, const void* gsrc) {
    asm volatile("cp.async.cg.shared.global [%0], [%1], 16;"
                 :: "r"(dst), "l"(__cvta_generic_to_global(gsrc)) : "memory");
}
__device__ __forceinline__ void cp_commit() {
    asm volatile("cp.async.commit_group;" ::: "memory");
}
template <int N>
__device__ __forceinline__ void cp_wait() {
    asm volatile("cp.async.wait_group %0;" :: "n"(N) : "memory");
}

// ---------------------------------------------------------------------------
// Transpose both fmaps: (B,C,HW) fp32 -> (B,HW,C) fp16, one launch
// ---------------------------------------------------------------------------
__global__ void transpose_both_kernel(const float* __restrict__ in1,
                                      const float* __restrict__ in2) {
    __shared__ float tile[32][33];
    int z   = blockIdx.z;                // 0..2*BB-1
    int b   = z & (BB - 1);
    const float* in = (z < BB) ? in1 : in2;
    __half* outp    = (z < BB) ? g_f1h : g_f2h;
    int hw0 = blockIdx.x*32, c0 = blockIdx.y*32;
    int tx = threadIdx.x, ty = threadIdx.y;
#pragma unroll
    for (int i = 0; i < 32; i += 8)
        tile[ty + i][tx] = in[(b*CC + c0 + ty + i) * HWC + hw0 + tx];
    __syncthreads();
#pragma unroll
    for (int i = 0; i < 32; i += 8)
        outp[((size_t)b*HWC + hw0 + ty + i) * CC + c0 + tx] =
            __float2half_rn(tile[tx][ty + i]);
}

// ---------------------------------------------------------------------------
// Pool f2 features to level-1 grid: f2l1[b, y1*32+x1, c] = mean of 2x2 f2
// ---------------------------------------------------------------------------
__global__ void pool_f2_kernel() {
    int idx = blockIdx.x * blockDim.x + threadIdx.x;
    if (idx >= BB * 1024 * (CC/2)) return;
    int c2 = idx & 127;
    int j  = (idx >> 7) & 1023;
    int b  = idx >> 17;
    int y1 = j >> 5, x1 = j & 31;
    const __half2* base = (const __half2*)g_f2h + (size_t)b * HWC * (CC/2);
    float2 a  = __half22float2(base[((2*y1  )*64 + 2*x1  ) * 128 + c2]);
    float2 bb = __half22float2(base[((2*y1  )*64 + 2*x1+1) * 128 + c2]);
    float2 c  = __half22float2(base[((2*y1+1)*64 + 2*x1  ) * 128 + c2]);
    float2 d  = __half22float2(base[((2*y1+1)*64 + 2*x1+1) * 128 + c2]);
    ((__half2*)g_f2l1)[idx] =
        __floats2half2_rn(0.25f * (a.x + bb.x + c.x + d.x),
                          0.25f * (a.y + bb.y + c.y + d.y));
}

// ---------------------------------------------------------------------------
// Pipelined GEMM (mma.sync, 32x64 warp tiles, 3-stage cp.async):
// c1[b, i, j1] = <f1[i], f2l1[j1]> / 16, M=4096, N=1024, K=256.
// ---------------------------------------------------------------------------
__global__ __launch_bounds__(256, 2)
void gemm_l1_kernel() {
    extern __shared__ __align__(16) char dsm[];
    uint32_t raw = smem_u32(dsm);
    uint32_t sb  = (raw + 1023u) & ~1023u;
    char*    smp = dsm + (sb - raw);

    int tid = threadIdx.x;
    int lid = tid & 31;
    int w   = tid >> 5;
    int wm  = w & 3;                          // M group (4 x 32)
    int wn  = w >> 2;                         // N group (2 x 64)
    int b   = blockIdx.z;
    int i0  = blockIdx.y * TM;
    int j0  = blockIdx.x * TN;

    const uint4* gA = (const uint4*)(g_f1h  + ((size_t)(b*HWC  + i0)) * CC);
    const uint4* gB = (const uint4*)(g_f2l1 + ((size_t)(b*1024 + j0)) * CC);

    auto load_stage = [&](int st, int kc) {
        uint32_t sS = sb + st * STAGE_BYTES;
#pragma unroll
        for (int i = 0; i < 4; i++) {
            int idx = tid + i * 256;
            int r = idx >> 3, cl = idx & 7;
            uint32_t off = (uint32_t)r * 128u + (uint32_t)((cl ^ (r & 7)) << 4);
            cp16(sS + off, gA + r * 32 + kc * 8 + cl);
        }
#pragma unroll
        for (int i = 0; i < 4; i++) {
            int idx = tid + i * 256;
            int r = idx >> 3, cl = idx & 7;
            uint32_t off = (uint32_t)r * 128u + (uint32_t)((cl ^ (r & 7)) << 4);
            cp16(sS + TM*KC*2 + off, gB + r * 32 + kc * 8 + cl);
        }
        cp_commit();
    };

    float acc[2][8][4];
#pragma unroll
    for (int mi = 0; mi < 2; mi++)
#pragma unroll
        for (int j = 0; j < 8; j++)
#pragma unroll
            for (int u = 0; u < 4; u++) acc[mi][j][u] = 0.f;

    int m0 = wm * 32;
    int nb = wn * 64;
    int arow = m0 + (lid & 15);
    int acb  = lid >> 4;
    int brow = nb + (lid & 7) + ((lid >> 4) << 3);
    int bcb  = (lid >> 3) & 1;

    load_stage(0, 0);
    load_stage(1, 1);

#pragma unroll
    for (int kc = 0; kc < 4; kc++) {
        if (kc < 3) cp_wait<1>(); else cp_wait<0>();
        __syncthreads();
        if (kc < 2) load_stage((kc + 2) % NSTAGE, kc + 2);

        uint32_t sA = sb + (kc % NSTAGE) * STAGE_BYTES;
        uint32_t sB = sA + TM*KC*2;
#pragma unroll
        for (int ks = 0; ks < 4; ks++) {
            uint32_t a[2][4];
#pragma unroll
            for (int mi = 0; mi < 2; mi++) {
                int row = arow + mi * 16;
                int ch  = ks * 2 + acb;
                uint32_t addr = sA + (uint32_t)row * 128u
                              + (uint32_t)((ch ^ (row & 7)) << 4);
                asm volatile(
                    "ldmatrix.sync.aligned.m8n8.x4.shared.b16 {%0,%1,%2,%3}, [%4];"
                    : "=r"(a[mi][0]), "=r"(a[mi][1]), "=r"(a[mi][2]), "=r"(a[mi][3])
                    : "r"(addr));
            }
            uint32_t bf[4][4];
#pragma unroll
            for (int ng = 0; ng < 4; ng++) {
                int row = brow + ng * 16;
                int ch  = ks * 2 + bcb;
                uint32_t addr = sB + (uint32_t)row * 128u
                              + (uint32_t)((ch ^ (row & 7)) << 4);
                asm volatile(
                    "ldmatrix.sync.aligned.m8n8.x4.shared.b16 {%0,%1,%2,%3}, [%4];"
                    : "=r"(bf[ng][0]), "=r"(bf[ng][1]), "=r"(bf[ng][2]), "=r"(bf[ng][3])
                    : "r"(addr));
            }
#pragma unroll
            for (int mi = 0; mi < 2; mi++)
#pragma unroll
                for (int j = 0; j < 8; j++) {
                    int ng = j >> 1, pr = (j & 1) * 2;
                    asm volatile(
                        "mma.sync.aligned.m16n8k16.row.col.f32.f16.f16.f32 "
                        "{%0,%1,%2,%3}, {%4,%5,%6,%7}, {%8,%9}, {%0,%1,%2,%3};"
                        : "+f"(acc[mi][j][0]), "+f"(acc[mi][j][1]),
                          "+f"(acc[mi][j][2]), "+f"(acc[mi][j][3])
                        : "r"(a[mi][0]), "r"(a[mi][1]), "r"(a[mi][2]), "r"(a[mi][3]),
                          "r"(bf[ng][pr]), "r"(bf[ng][pr + 1]));
                }
        }
        __syncthreads();
    }

    // ---- epilogue: fragments -> smem tile (128x128 fp16) -> c1 ----
    {
        __half* epi = (__half*)smp;           // 32 KB, reuse stage 0
        const float s = 0.0625f;              // 1/sqrt(256)
#pragma unroll
        for (int mi = 0; mi < 2; mi++)
#pragma unroll
            for (int j = 0; j < 8; j++) {
                int n = nb + j * 8 + (lid & 3) * 2;
                int m = m0 + mi * 16 + (lid >> 2);
                *(__half2*)(epi + m * 128 + n) =
                    __floats2half2_rn(acc[mi][j][0] * s, acc[mi][j][1] * s);
                *(__half2*)(epi + (m + 8) * 128 + n) =
                    __floats2half2_rn(acc[mi][j][2] * s, acc[mi][j][3] * s);
            }
        __syncthreads();
        const uint4* ev = (const uint4*)epi;
#pragma unroll
        for (int it = 0; it < 8; it++) {
            int idx = tid + it * 256;         // 2048 uint4
            int r = idx >> 4, c = idx & 15;
            *(uint4*)(g_c1 + ((size_t)(b*HWC + i0 + r)) * 1024 + j0 + c * 8) =
                ev[idx];
        }
    }
}

// ---------------------------------------------------------------------------
// Direct level-0 window dots: w0[q][t] = <f1_q, f2[tap_t]> / 16 (0 if OOB).
// Grid (512, 2): blockIdx.y selects a 50-tap half (occupancy: 1024 blocks).
// Block = 16 queries; 32 groups of 8 lanes; lane owns 32 channels.
// ---------------------------------------------------------------------------
__global__ __launch_bounds__(256)
void w0_sample_kernel(const float* __restrict__ coords) {
    int bidx = blockIdx.x;
    int b    = bidx >> 8;
    int hw0  = (bidx & 255) * QT;
    int t0   = blockIdx.y * 50;              // tap range [t0, t0+50)
    int tid  = threadIdx.x;
    int sub  = tid & 7;
    int grp  = tid >> 3;
    int q    = grp >> 1;
    int half = grp & 1;
    int n    = b * HWC + hw0 + q;

    float rf1[32];
    {
        const uint4* p = (const uint4*)(g_f1h + (size_t)n * CC + sub * 32);
#pragma unroll
        for (int u = 0; u < 4; u++) {
            uint4 h8 = p[u];
            float2 f;
            f = __half22float2(*(const __half2*)&h8.x);
            rf1[u*8+0] = f.x; rf1[u*8+1] = f.y;
            f = __half22float2(*(const __half2*)&h8.y);
            rf1[u*8+2] = f.x; rf1[u*8+3] = f.y;
            f = __half22float2(*(const __half2*)&h8.z);
            rf1[u*8+4] = f.x; rf1[u*8+5] = f.y;
            f = __half22float2(*(const __half2*)&h8.w);
            rf1[u*8+6] = f.x; rf1[u*8+7] = f.y;
        }
    }
    float xq = coords[(b*2 + 0) * HWC + hw0 + q];
    float yq = coords[(b*2 + 1) * HWC + hw0 + q];
    int bx = (int)floorf(xq) - RAD;
    int by = (int)floorf(yq) - RAD;
    const __half* f2b = g_f2h + (size_t)b * HWC * CC;

#pragma unroll 5
    for (int t = t0 + half; t < t0 + 50; t += 2) {
        int ty = (t * 205) >> 11;            // /10
        int tx = t - ty * 10;
        int ix = bx + tx, iy = by + ty;
        float acc0 = 0.f, acc1 = 0.f;
        if (((unsigned)ix < 64u) & ((unsigned)iy < 64u)) {
            const uint4* p =
                (const uint4*)(f2b + ((size_t)(iy*64 + ix)) * CC + sub * 32);
            uint4 h0 = p[0], h1 = p[1], h2 = p[2], h3 = p[3];
            float2 f;
            f = __half22float2(*(const __half2*)&h0.x);
            acc0 = fmaf(rf1[ 0], f.x, acc0); acc0 = fmaf(rf1[ 1], f.y, acc0);
            f = __half22float2(*(const __half2*)&h0.y);
            acc0 = fmaf(rf1[ 2], f.x, acc0); acc0 = fmaf(rf1[ 3], f.y, acc0);
            f = __half22float2(*(const __half2*)&h0.z);
            acc0 = fmaf(rf1[ 4], f.x, acc0); acc0 = fmaf(rf1[ 5], f.y, acc0);
            f = __half22float2(*(const __half2*)&h0.w);
            acc0 = fmaf(rf1[ 6], f.x, acc0); acc0 = fmaf(rf1[ 7], f.y, acc0);
            f = __half22float2(*(const __half2*)&h1.x);
            acc1 = fmaf(rf1[ 8], f.x, acc1); acc1 = fmaf(rf1[ 9], f.y, acc1);
            f = __half22float2(*(const __half2*)&h1.y);
            acc1 = fmaf(rf1[10], f.x, acc1); acc1 = fmaf(rf1[11], f.y, acc1);
            f = __half22float2(*(const __half2*)&h1.z);
            acc1 = fmaf(rf1[12], f.x, acc1); acc1 = fmaf(rf1[13], f.y, acc1);
            f = __half22float2(*(const __half2*)&h1.w);
            acc1 = fmaf(rf1[14], f.x, acc1); acc1 = fmaf(rf1[15], f.y, acc1);
            f = __half22float2(*(const __half2*)&h2.x);
            acc0 = fmaf(rf1[16], f.x, acc0); acc0 = fmaf(rf1[17], f.y, acc0);
            f = __half22float2(*(const __half2*)&h2.y);
            acc0 = fmaf(rf1[18], f.x, acc0); acc0 = fmaf(rf1[19], f.y, acc0);
            f = __half22float2(*(const __half2*)&h2.z);
            acc0 = fmaf(rf1[20], f.x, acc0); acc0 = fmaf(rf1[21], f.y, acc0);
            f = __half22float2(*(const __half2*)&h2.w);
            acc0 = fmaf(rf1[22], f.x, acc0); acc0 = fmaf(rf1[23], f.y, acc0);
            f = __half22float2(*(const __half2*)&h3.x);
            acc1 = fmaf(rf1[24], f.x, acc1); acc1 = fmaf(rf1[25], f.y, acc1);
            f = __half22float2(*(const __half2*)&h3.y);
            acc1 = fmaf(rf1[26], f.x, acc1); acc1 = fmaf(rf1[27], f.y, acc1);
            f = __half22float2(*(const __half2*)&h3.z);
            acc1 = fmaf(rf1[28], f.x, acc1); acc1 = fmaf(rf1[29], f.y, acc1);
            f = __half22float2(*(const __half2*)&h3.w);
            acc1 = fmaf(rf1[30], f.x, acc1); acc1 = fmaf(rf1[31], f.y, acc1);
        }
        float acc = acc0 + acc1;
        acc += __shfl_down_sync(0xffffffffu, acc, 4);
        acc += __shfl_down_sync(0xffffffffu, acc, 2);
        acc += __shfl_down_sync(0xffffffffu, acc, 1);
        if (sub == 0)
            g_w0[(size_t)n * WS + t] = __float2half_rn(acc * 0.0625f);
    }
}

// ---------------------------------------------------------------------------
// Merged pool+sample: block = 16 queries. l1 rows -> smem; l2/l3 pooled in
// smem (fp32); windows staged; 324 bilinear outputs/query. No divisions.
// ---------------------------------------------------------------------------
__global__ __launch_bounds__(256)
void pool_sample_kernel(const float* __restrict__ coords,
                        float* __restrict__ out) {
    extern __shared__ __align__(16) char sm[];
    __half* sl1 = (__half*)(sm + SMP_SL1);     // [16][1024]
    float*  sl2 = (float*) (sm + SMP_SL2);     // [16][256]
    float*  sl3 = (float*) (sm + SMP_SL3);     // [16][64]
    float*  sW  = (float*) (sm + SMP_SW);      // [16][400]
    __shared__ float sX[QT], sY[QT];

    int bidx = blockIdx.x;                     // 0..511
    int b    = bidx >> 8;
    int hw0  = (bidx & 255) * QT;
    int n0   = b * HWC + hw0;
    int tid  = threadIdx.x;

    if (tid < QT) {
        sX[tid] = coords[(b*2 + 0) * HWC + hw0 + tid];
        sY[tid] = coords[(b*2 + 1) * HWC + hw0 + tid];
    }

    // load 16 l1 rows (contiguous 32 KB)
    {
        const uint4* src = (const uint4*)(g_c1 + (size_t)n0 * 1024);
        uint4* dst = (uint4*)sl1;
#pragma unroll
        for (int i = 0; i < 8; i++) dst[tid + i*256] = src[tid + i*256];
    }
    __syncthreads();

    // l2 pool (fp32): 4096 cells
#pragma unroll
    for (int i = 0; i < 16; i++) {
        int c = tid + i*256;
        int q = c >> 8, r = c & 255;
        int y = r >> 4, x = r & 15;
        const __half* base = sl1 + q*1024 + (2*y)*32 + 2*x;
        float2 p0 = __half22float2(*(const __half2*)base);
        float2 p1 = __half22float2(*(const __half2*)(base + 32));
        sl2[c] = 0.25f * (p0.x + p0.y + p1.x + p1.y);
    }
    __syncthreads();

    // l3 pool: 1024 cells
#pragma unroll
    for (int i = 0; i < 4; i++) {
        int c = tid + i*256;
        int q = c >> 6, r = c & 63;
        int y = r >> 3, x = r & 7;
        const float* base = sl2 + q*256 + (2*y)*16 + 2*x;
        sl3[c] = 0.25f * (base[0] + base[1] + base[16] + base[17]);
    }
    __syncthreads();

    // stage windows: per level, 1600 = 16 q x 100 taps
#pragma unroll
    for (int l = 0; l < 4; l++) {
#pragma unroll
        for (int i = 0; i < 7; i++) {
            int idx = tid + i*256;
            if (idx < 1600) {
                int q  = (int)(((unsigned)idx * 5243u) >> 19);   // /100
                int t  = idx - q * 100;
                int ty = (int)(((unsigned)t * 205u) >> 11);      // /10
                int tx = t - ty * 10;
                float sc = 1.0f / (float)(1 << l);
                float xc = sX[q] * sc, yc = sY[q] * sc;
                int ix = (int)floorf(xc) - RAD + tx;
                int iy = (int)floorf(yc) - RAD + ty;
                int Wl = 64 >> l;
                float v = 0.f;
                if (ix >= 0 && ix < Wl && iy >= 0 && iy < Wl) {
                    if      (l == 0) v = __half2float(g_w0[(size_t)(n0+q)*WS + t]);
                    else if (l == 1) v = __half2float(sl1[q*1024 + iy*32 + ix]);
                    else if (l == 2) v = sl2[q*256 + iy*16 + ix];
                    else             v = sl3[q*64 + iy*8 + ix];
                }
                sW[q*400 + l*100 + t] = v;
            }
        }
    }
    __syncthreads();

    // outputs: per level, 1296 = 81 taps x 16 q
#pragma unroll
    for (int l = 0; l < 4; l++) {
        float sc = 1.0f / (float)(1 << l);
#pragma unroll
        for (int i = 0; i < 6; i++) {
            int idx = tid + i*256;
            if (idx < 1296) {
                int k  = idx >> 4;
                int qq = idx & 15;
                int cx = (int)(((unsigned)k * 57u) >> 9);        // /9
                int ry = k - cx * 9;
                float xq = sX[qq] * sc;
                float yq = sY[qq] * sc;
                float fx = xq - floorf(xq);
                float fy = yq - floorf(yq);
                const float* W = sW + qq*400 + l*100;
                float v00 = W[ ry      * 10 + cx    ];
                float v01 = W[ ry      * 10 + cx + 1];
                float v10 = W[(ry + 1) * 10 + cx    ];
                float v11 = W[(ry + 1) * 10 + cx + 1];
                float v = (1.f - fy) * ((1.f - fx) * v00 + fx * v01)
                        +        fy  * ((1.f - fx) * v10 + fx * v11);
                out[((size_t)(b * 324 + l * 81 + k)) * HWC + hw0 + qq] = v;
            }
        }
    }
}

// ---------------------------------------------------------------------------
extern "C" void kernel_launch(void* const* d_in, const int* in_sizes, int n_in,
                              void* d_out, int out_size) {
    const float* fmap1  = (const float*)d_in[0];
    const float* fmap2  = (const float*)d_in[1];
    const float* coords = (const float*)d_in[2];
    float* out = (float*)d_out;

    cudaFuncSetAttribute(gemm_l1_kernel,
                         cudaFuncAttributeMaxDynamicSharedMemorySize,
                         GEMM_SMEM_BYTES);
    cudaFuncSetAttribute(pool_sample_kernel,
                         cudaFuncAttributeMaxDynamicSharedMemorySize,
                         SAMPLE_SMEM_BYTES);

    dim3 tgrid(HWC / 32, CC / 32, 2*BB);
    dim3 tblk(32, 8);
    transpose_both_kernel<<<tgrid, tblk>>>(fmap1, fmap2);

    pool_f2_kernel<<<(BB*1024*(CC/2) + 255) / 256, 256>>>();

    dim3 ggrid(1024 / TN, HWC / TM, BB);  // (8, 32, 2)
    gemm_l1_kernel<<<ggrid, 256, GEMM_SMEM_BYTES>>>();

    dim3 wgrid(NQ / QT, 2);               // (512, 2) — 50 taps per block
    w0_sample_kernel<<<wgrid, 256>>>(coords);

    pool_sample_kernel<<<NQ / QT, 256, SAMPLE_SMEM_BYTES>>>(coords, out);
}

// round 14
// speedup vs baseline: 1.2189x; 1.1955x over previous
#include <cuda_runtime.h>
#include <cuda_fp16.h>
#include <cstdint>

// Problem constants
#define BB 2
#define CC 256
#define HH 64
#define WW 64
#define HWC (HH*WW)          // 4096
#define NQ (BB*HWC)          // 8192
#define NLVL 4
#define RAD 4
#define QT 16                // queries per tile
#define WS 112               // per-query w0 stride (100 used, padded)

// GEMM tiling: 128x128 block tile, 8 warps of 32x64, K chunks of 64, 3 stages
#define TM 128
#define TN 128
#define KC 64
#define NSTAGE 3
#define STAGE_BYTES ((TM+TN)*KC*2)           // 32 KB per stage
#define GEMM_SMEM_BYTES (NSTAGE*STAGE_BYTES + 1024)

// Merged pool+sample smem layout (dynamic)
#define SMP_SL1 0                            // __half [16][1024]  32 KB
#define SMP_SL2 32768                        // float  [16][256]   16 KB
#define SMP_SL3 49152                        // float  [16][64]     4 KB
#define SMP_SW  53248                        // float  [16][400]   25.6 KB
#define SAMPLE_SMEM_BYTES 78848

// Scratch (device globals; allocation-free rule)
__device__ __half g_f1h[BB*HWC*CC];          // (B, HW, C) fp16, 4 MB
__device__ __half g_f2h[BB*HWC*CC];          // (B, HW, C) fp16, 4 MB
__device__ __half g_f2l1[BB*1024*CC];        // pooled f2 (l1), 1 MB
__device__ __half g_c1[(size_t)NQ*32*32];    // corr lvl1 volume, 16.8 MB
__device__ __half g_w0[(size_t)NQ*WS];       // per-query l0 10x10 windows

__device__ __forceinline__ uint32_t smem_u32(const void* p) {
    uint32_t a;
    asm("{ .reg .u64 t; cvta.to.shared.u64 t, %1; cvt.u32.u64 %0, t; }"
        : "=r"(a) : "l"(p));
    return a;
}
__device__ __forceinline__ void cp16(uint32_t dst, const void* gsrc) {
    asm volatile("cp.async.cg.shared.global [%0], [%1], 16;"
                 :: "r"(dst), "l"(__cvta_generic_to_global(gsrc)) : "memory");
}
__device__ __forceinline__ void cp_commit() {
    asm volatile("cp.async.commit_group;" ::: "memory");
}
template <int N>
__device__ __forceinline__ void cp_wait() {
    asm volatile("cp.async.wait_group %0;" :: "n"(N) : "memory");
}

// ---------------------------------------------------------------------------
// Transpose both fmaps: (B,C,HW) fp32 -> (B,HW,C) fp16, one launch
// ---------------------------------------------------------------------------
__global__ void transpose_both_kernel(const float* __restrict__ in1,
                                      const float* __restrict__ in2) {
    __shared__ float tile[32][33];
    int z   = blockIdx.z;                // 0..2*BB-1
    int b   = z & (BB - 1);
    const float* in = (z < BB) ? in1 : in2;
    __half* outp    = (z < BB) ? g_f1h : g_f2h;
    int hw0 = blockIdx.x*32, c0 = blockIdx.y*32;
    int tx = threadIdx.x, ty = threadIdx.y;
#pragma unroll
    for (int i = 0; i < 32; i += 8)
        tile[ty + i][tx] = in[(b*CC + c0 + ty + i) * HWC + hw0 + tx];
    __syncthreads();
#pragma unroll
    for (int i = 0; i < 32; i += 8)
        outp[((size_t)b*HWC + hw0 + ty + i) * CC + c0 + tx] =
            __float2half_rn(tile[tx][ty + i]);
}

// ---------------------------------------------------------------------------
// Pool f2 features to level-1 grid: f2l1[b, y1*32+x1, c] = mean of 2x2 f2
// ---------------------------------------------------------------------------
__global__ void pool_f2_kernel() {
    int idx = blockIdx.x * blockDim.x + threadIdx.x;
    if (idx >= BB * 1024 * (CC/2)) return;
    int c2 = idx & 127;
    int j  = (idx >> 7) & 1023;
    int b  = idx >> 17;
    int y1 = j >> 5, x1 = j & 31;
    const __half2* base = (const __half2*)g_f2h + (size_t)b * HWC * (CC/2);
    float2 a  = __half22float2(base[((2*y1  )*64 + 2*x1  ) * 128 + c2]);
    float2 bb = __half22float2(base[((2*y1  )*64 + 2*x1+1) * 128 + c2]);
    float2 c  = __half22float2(base[((2*y1+1)*64 + 2*x1  ) * 128 + c2]);
    float2 d  = __half22float2(base[((2*y1+1)*64 + 2*x1+1) * 128 + c2]);
    ((__half2*)g_f2l1)[idx] =
        __floats2half2_rn(0.25f * (a.x + bb.x + c.x + d.x),
                          0.25f * (a.y + bb.y + c.y + d.y));
}

// ---------------------------------------------------------------------------
// Pipelined GEMM (mma.sync, 32x64 warp tiles, 3-stage cp.async):
// c1[b, i, j1] = <f1[i], f2l1[j1]> / 16, M=4096, N=1024, K=256.
// ---------------------------------------------------------------------------
__global__ __launch_bounds__(256, 2)
void gemm_l1_kernel() {
    extern __shared__ __align__(16) char dsm[];
    uint32_t raw = smem_u32(dsm);
    uint32_t sb  = (raw + 1023u) & ~1023u;
    char*    smp = dsm + (sb - raw);

    int tid = threadIdx.x;
    int lid = tid & 31;
    int w   = tid >> 5;
    int wm  = w & 3;                          // M group (4 x 32)
    int wn  = w >> 2;                         // N group (2 x 64)
    int b   = blockIdx.z;
    int i0  = blockIdx.y * TM;
    int j0  = blockIdx.x * TN;

    const uint4* gA = (const uint4*)(g_f1h  + ((size_t)(b*HWC  + i0)) * CC);
    const uint4* gB = (const uint4*)(g_f2l1 + ((size_t)(b*1024 + j0)) * CC);

    auto load_stage = [&](int st, int kc) {
        uint32_t sS = sb + st * STAGE_BYTES;
#pragma unroll
        for (int i = 0; i < 4; i++) {
            int idx = tid + i * 256;
            int r = idx >> 3, cl = idx & 7;
            uint32_t off = (uint32_t)r * 128u + (uint32_t)((cl ^ (r & 7)) << 4);
            cp16(sS + off, gA + r * 32 + kc * 8 + cl);
        }
#pragma unroll
        for (int i = 0; i < 4; i++) {
            int idx = tid + i * 256;
            int r = idx >> 3, cl = idx & 7;
            uint32_t off = (uint32_t)r * 128u + (uint32_t)((cl ^ (r & 7)) << 4);
            cp16(sS + TM*KC*2 + off, gB + r * 32 + kc * 8 + cl);
        }
        cp_commit();
    };

    float acc[2][8][4];
#pragma unroll
    for (int mi = 0; mi < 2; mi++)
#pragma unroll
        for (int j = 0; j < 8; j++)
#pragma unroll
            for (int u = 0; u < 4; u++) acc[mi][j][u] = 0.f;

    int m0 = wm * 32;
    int nb = wn * 64;
    int arow = m0 + (lid & 15);
    int acb  = lid >> 4;
    int brow = nb + (lid & 7) + ((lid >> 4) << 3);
    int bcb  = (lid >> 3) & 1;

    load_stage(0, 0);
    load_stage(1, 1);

#pragma unroll
    for (int kc = 0; kc < 4; kc++) {
        if (kc < 3) cp_wait<1>(); else cp_wait<0>();
        __syncthreads();
        if (kc < 2) load_stage((kc + 2) % NSTAGE, kc + 2);

        uint32_t sA = sb + (kc % NSTAGE) * STAGE_BYTES;
        uint32_t sB = sA + TM*KC*2;
#pragma unroll
        for (int ks = 0; ks < 4; ks++) {
            uint32_t a[2][4];
#pragma unroll
            for (int mi = 0; mi < 2; mi++) {
                int row = arow + mi * 16;
                int ch  = ks * 2 + acb;
                uint32_t addr = sA + (uint32_t)row * 128u
                              + (uint32_t)((ch ^ (row & 7)) << 4);
                asm volatile(
                    "ldmatrix.sync.aligned.m8n8.x4.shared.b16 {%0,%1,%2,%3}, [%4];"
                    : "=r"(a[mi][0]), "=r"(a[mi][1]), "=r"(a[mi][2]), "=r"(a[mi][3])
                    : "r"(addr));
            }
            uint32_t bf[4][4];
#pragma unroll
            for (int ng = 0; ng < 4; ng++) {
                int row = brow + ng * 16;
                int ch  = ks * 2 + bcb;
                uint32_t addr = sB + (uint32_t)row * 128u
                              + (uint32_t)((ch ^ (row & 7)) << 4);
                asm volatile(
                    "ldmatrix.sync.aligned.m8n8.x4.shared.b16 {%0,%1,%2,%3}, [%4];"
                    : "=r"(bf[ng][0]), "=r"(bf[ng][1]), "=r"(bf[ng][2]), "=r"(bf[ng][3])
                    : "r"(addr));
            }
#pragma unroll
            for (int mi = 0; mi < 2; mi++)
#pragma unroll
                for (int j = 0; j < 8; j++) {
                    int ng = j >> 1, pr = (j & 1) * 2;
                    asm volatile(
                        "mma.sync.aligned.m16n8k16.row.col.f32.f16.f16.f32 "
                        "{%0,%1,%2,%3}, {%4,%5,%6,%7}, {%8,%9}, {%0,%1,%2,%3};"
                        : "+f"(acc[mi][j][0]), "+f"(acc[mi][j][1]),
                          "+f"(acc[mi][j][2]), "+f"(acc[mi][j][3])
                        : "r"(a[mi][0]), "r"(a[mi][1]), "r"(a[mi][2]), "r"(a[mi][3]),
                          "r"(bf[ng][pr]), "r"(bf[ng][pr + 1]));
                }
        }
        __syncthreads();
    }

    // ---- epilogue: fragments -> smem tile (128x128 fp16) -> c1 ----
    {
        __half* epi = (__half*)smp;           // 32 KB, reuse stage 0
        const float s = 0.0625f;              // 1/sqrt(256)
#pragma unroll
        for (int mi = 0; mi < 2; mi++)
#pragma unroll
            for (int j = 0; j < 8; j++) {
                int n = nb + j * 8 + (lid & 3) * 2;
                int m = m0 + mi * 16 + (lid >> 2);
                *(__half2*)(epi + m * 128 + n) =
                    __floats2half2_rn(acc[mi][j][0] * s, acc[mi][j][1] * s);
                *(__half2*)(epi + (m + 8) * 128 + n) =
                    __floats2half2_rn(acc[mi][j][2] * s, acc[mi][j][3] * s);
            }
        __syncthreads();
        const uint4* ev = (const uint4*)epi;
#pragma unroll
        for (int it = 0; it < 8; it++) {
            int idx = tid + it * 256;         // 2048 uint4
            int r = idx >> 4, c = idx & 15;
            *(uint4*)(g_c1 + ((size_t)(b*HWC + i0 + r)) * 1024 + j0 + c * 8) =
                ev[idx];
        }
    }
}

// ---------------------------------------------------------------------------
// Direct level-0 window dots: w0[q][t] = <f1_q, f2[tap_t]> / 16 (0 if OOB).
// Grid (512, 2); block = 16 queries; 32 groups of 8 lanes.
// COALESCED chunk->lane mapping: for load iteration u, lane sub owns the
// 16B chunk (u*8 + sub) of the 512B row -> each group LDG.128 is one
// contiguous 128B wavefront. rf1 holds f1 chunks with the same mapping.
// ---------------------------------------------------------------------------
__global__ __launch_bounds__(256)
void w0_sample_kernel(const float* __restrict__ coords) {
    int bidx = blockIdx.x;
    int b    = bidx >> 8;
    int hw0  = (bidx & 255) * QT;
    int t0   = blockIdx.y * 50;              // tap range [t0, t0+50)
    int tid  = threadIdx.x;
    int sub  = tid & 7;
    int grp  = tid >> 3;
    int q    = grp >> 1;
    int half = grp & 1;
    int n    = b * HWC + hw0 + q;

    // f1 chunks {u*8+sub}, coalesced 128B per group per iteration
    float rf1[32];
    {
        const uint4* p = (const uint4*)(g_f1h + (size_t)n * CC);
#pragma unroll
        for (int u = 0; u < 4; u++) {
            uint4 h8 = p[u * 8 + sub];
            float2 f;
            f = __half22float2(*(const __half2*)&h8.x);
            rf1[u*8+0] = f.x; rf1[u*8+1] = f.y;
            f = __half22float2(*(const __half2*)&h8.y);
            rf1[u*8+2] = f.x; rf1[u*8+3] = f.y;
            f = __half22float2(*(const __half2*)&h8.z);
            rf1[u*8+4] = f.x; rf1[u*8+5] = f.y;
            f = __half22float2(*(const __half2*)&h8.w);
            rf1[u*8+6] = f.x; rf1[u*8+7] = f.y;
        }
    }
    float xq = coords[(b*2 + 0) * HWC + hw0 + q];
    float yq = coords[(b*2 + 1) * HWC + hw0 + q];
    int bx = (int)floorf(xq) - RAD;
    int by = (int)floorf(yq) - RAD;
    const __half* f2b = g_f2h + (size_t)b * HWC * CC;

#pragma unroll 5
    for (int t = t0 + half; t < t0 + 50; t += 2) {
        int ty = (t * 205) >> 11;            // /10
        int tx = t - ty * 10;
        int ix = bx + tx, iy = by + ty;
        float acc0 = 0.f, acc1 = 0.f;
        if (((unsigned)ix < 64u) & ((unsigned)iy < 64u)) {
            const uint4* p =
                (const uint4*)(f2b + ((size_t)(iy*64 + ix)) * CC);
            // coalesced: iteration u loads chunk u*8+sub (contiguous per group)
            uint4 h0 = p[0*8 + sub], h1 = p[1*8 + sub];
            uint4 h2 = p[2*8 + sub], h3 = p[3*8 + sub];
            float2 f;
            f = __half22float2(*(const __half2*)&h0.x);
            acc0 = fmaf(rf1[ 0], f.x, acc0); acc0 = fmaf(rf1[ 1], f.y, acc0);
            f = __half22float2(*(const __half2*)&h0.y);
            acc0 = fmaf(rf1[ 2], f.x, acc0); acc0 = fmaf(rf1[ 3], f.y, acc0);
            f = __half22float2(*(const __half2*)&h0.z);
            acc0 = fmaf(rf1[ 4], f.x, acc0); acc0 = fmaf(rf1[ 5], f.y, acc0);
            f = __half22float2(*(const __half2*)&h0.w);
            acc0 = fmaf(rf1[ 6], f.x, acc0); acc0 = fmaf(rf1[ 7], f.y, acc0);
            f = __half22float2(*(const __half2*)&h1.x);
            acc1 = fmaf(rf1[ 8], f.x, acc1); acc1 = fmaf(rf1[ 9], f.y, acc1);
            f = __half22float2(*(const __half2*)&h1.y);
            acc1 = fmaf(rf1[10], f.x, acc1); acc1 = fmaf(rf1[11], f.y, acc1);
            f = __half22float2(*(const __half2*)&h1.z);
            acc1 = fmaf(rf1[12], f.x, acc1); acc1 = fmaf(rf1[13], f.y, acc1);
            f = __half22float2(*(const __half2*)&h1.w);
            acc1 = fmaf(rf1[14], f.x, acc1); acc1 = fmaf(rf1[15], f.y, acc1);
            f = __half22float2(*(const __half2*)&h2.x);
            acc0 = fmaf(rf1[16], f.x, acc0); acc0 = fmaf(rf1[17], f.y, acc0);
            f = __half22float2(*(const __half2*)&h2.y);
            acc0 = fmaf(rf1[18], f.x, acc0); acc0 = fmaf(rf1[19], f.y, acc0);
            f = __half22float2(*(const __half2*)&h2.z);
            acc0 = fmaf(rf1[20], f.x, acc0); acc0 = fmaf(rf1[21], f.y, acc0);
            f = __half22float2(*(const __half2*)&h2.w);
            acc0 = fmaf(rf1[22], f.x, acc0); acc0 = fmaf(rf1[23], f.y, acc0);
            f = __half22float2(*(const __half2*)&h3.x);
            acc1 = fmaf(rf1[24], f.x, acc1); acc1 = fmaf(rf1[25], f.y, acc1);
            f = __half22float2(*(const __half2*)&h3.y);
            acc1 = fmaf(rf1[26], f.x, acc1); acc1 = fmaf(rf1[27], f.y, acc1);
            f = __half22float2(*(const __half2*)&h3.z);
            acc1 = fmaf(rf1[28], f.x, acc1); acc1 = fmaf(rf1[29], f.y, acc1);
            f = __half22float2(*(const __half2*)&h3.w);
            acc1 = fmaf(rf1[30], f.x, acc1); acc1 = fmaf(rf1[31], f.y, acc1);
        }
        float acc = acc0 + acc1;
        acc += __shfl_down_sync(0xffffffffu, acc, 4);
        acc += __shfl_down_sync(0xffffffffu, acc, 2);
        acc += __shfl_down_sync(0xffffffffu, acc, 1);
        if (sub == 0)
            g_w0[(size_t)n * WS + t] = __float2half_rn(acc * 0.0625f);
    }
}

// ---------------------------------------------------------------------------
// Merged pool+sample: block = 16 queries. l1 rows -> smem; l2/l3 pooled in
// smem (fp32); windows staged; 324 bilinear outputs/query. No divisions.
// ---------------------------------------------------------------------------
__global__ __launch_bounds__(256)
void pool_sample_kernel(const float* __restrict__ coords,
                        float* __restrict__ out) {
    extern __shared__ __align__(16) char sm[];
    __half* sl1 = (__half*)(sm + SMP_SL1);     // [16][1024]
    float*  sl2 = (float*) (sm + SMP_SL2);     // [16][256]
    float*  sl3 = (float*) (sm + SMP_SL3);     // [16][64]
    float*  sW  = (float*) (sm + SMP_SW);      // [16][400]
    __shared__ float sX[QT], sY[QT];

    int bidx = blockIdx.x;                     // 0..511
    int b    = bidx >> 8;
    int hw0  = (bidx & 255) * QT;
    int n0   = b * HWC + hw0;
    int tid  = threadIdx.x;

    if (tid < QT) {
        sX[tid] = coords[(b*2 + 0) * HWC + hw0 + tid];
        sY[tid] = coords[(b*2 + 1) * HWC + hw0 + tid];
    }

    // load 16 l1 rows (contiguous 32 KB)
    {
        const uint4* src = (const uint4*)(g_c1 + (size_t)n0 * 1024);
        uint4* dst = (uint4*)sl1;
#pragma unroll
        for (int i = 0; i < 8; i++) dst[tid + i*256] = src[tid + i*256];
    }
    __syncthreads();

    // l2 pool (fp32): 4096 cells
#pragma unroll
    for (int i = 0; i < 16; i++) {
        int c = tid + i*256;
        int q = c >> 8, r = c & 255;
        int y = r >> 4, x = r & 15;
        const __half* base = sl1 + q*1024 + (2*y)*32 + 2*x;
        float2 p0 = __half22float2(*(const __half2*)base);
        float2 p1 = __half22float2(*(const __half2*)(base + 32));
        sl2[c] = 0.25f * (p0.x + p0.y + p1.x + p1.y);
    }
    __syncthreads();

    // l3 pool: 1024 cells
#pragma unroll
    for (int i = 0; i < 4; i++) {
        int c = tid + i*256;
        int q = c >> 6, r = c & 63;
        int y = r >> 3, x = r & 7;
        const float* base = sl2 + q*256 + (2*y)*16 + 2*x;
        sl3[c] = 0.25f * (base[0] + base[1] + base[16] + base[17]);
    }
    __syncthreads();

    // stage windows: per level, 1600 = 16 q x 100 taps
#pragma unroll
    for (int l = 0; l < 4; l++) {
#pragma unroll
        for (int i = 0; i < 7; i++) {
            int idx = tid + i*256;
            if (idx < 1600) {
                int q  = (int)(((unsigned)idx * 5243u) >> 19);   // /100
                int t  = idx - q * 100;
                int ty = (int)(((unsigned)t * 205u) >> 11);      // /10
                int tx = t - ty * 10;
                float sc = 1.0f / (float)(1 << l);
                float xc = sX[q] * sc, yc = sY[q] * sc;
                int ix = (int)floorf(xc) - RAD + tx;
                int iy = (int)floorf(yc) - RAD + ty;
                int Wl = 64 >> l;
                float v = 0.f;
                if (ix >= 0 && ix < Wl && iy >= 0 && iy < Wl) {
                    if      (l == 0) v = __half2float(g_w0[(size_t)(n0+q)*WS + t]);
                    else if (l == 1) v = __half2float(sl1[q*1024 + iy*32 + ix]);
                    else if (l == 2) v = sl2[q*256 + iy*16 + ix];
                    else             v = sl3[q*64 + iy*8 + ix];
                }
                sW[q*400 + l*100 + t] = v;
            }
        }
    }
    __syncthreads();

    // outputs: per level, 1296 = 81 taps x 16 q
#pragma unroll
    for (int l = 0; l < 4; l++) {
        float sc = 1.0f / (float)(1 << l);
#pragma unroll
        for (int i = 0; i < 6; i++) {
            int idx = tid + i*256;
            if (idx < 1296) {
                int k  = idx >> 4;
                int qq = idx & 15;
                int cx = (int)(((unsigned)k * 57u) >> 9);        // /9
                int ry = k - cx * 9;
                float xq = sX[qq] * sc;
                float yq = sY[qq] * sc;
                float fx = xq - floorf(xq);
                float fy = yq - floorf(yq);
                const float* W = sW + qq*400 + l*100;
                float v00 = W[ ry      * 10 + cx    ];
                float v01 = W[ ry      * 10 + cx + 1];
                float v10 = W[(ry + 1) * 10 + cx    ];
                float v11 = W[(ry + 1) * 10 + cx + 1];
                float v = (1.f - fy) * ((1.f - fx) * v00 + fx * v01)
                        +        fy  * ((1.f - fx) * v10 + fx * v11);
                out[((size_t)(b * 324 + l * 81 + k)) * HWC + hw0 + qq] = v;
            }
        }
    }
}

// ---------------------------------------------------------------------------
extern "C" void kernel_launch(void* const* d_in, const int* in_sizes, int n_in,
                              void* d_out, int out_size) {
    const float* fmap1  = (const float*)d_in[0];
    const float* fmap2  = (const float*)d_in[1];
    const float* coords = (const float*)d_in[2];
    float* out = (float*)d_out;

    cudaFuncSetAttribute(gemm_l1_kernel,
                         cudaFuncAttributeMaxDynamicSharedMemorySize,
                         GEMM_SMEM_BYTES);
    cudaFuncSetAttribute(pool_sample_kernel,
                         cudaFuncAttributeMaxDynamicSharedMemorySize,
                         SAMPLE_SMEM_BYTES);

    dim3 tgrid(HWC / 32, CC / 32, 2*BB);
    dim3 tblk(32, 8);
    transpose_both_kernel<<<tgrid, tblk>>>(fmap1, fmap2);

    pool_f2_kernel<<<(BB*1024*(CC/2) + 255) / 256, 256>>>();

    dim3 ggrid(1024 / TN, HWC / TM, BB);  // (8, 32, 2)
    gemm_l1_kernel<<<ggrid, 256, GEMM_SMEM_BYTES>>>();

    dim3 wgrid(NQ / QT, 2);               // (512, 2) — 50 taps per block
    w0_sample_kernel<<<wgrid, 256>>>(coords);

    pool_sample_kernel<<<NQ / QT, 256, SAMPLE_SMEM_BYTES>>>(coords, out);
}

// round 15
// speedup vs baseline: 1.3980x; 1.1469x over previous
#include <cuda_runtime.h>
#include <cuda_fp16.h>
#include <cstdint>

// Problem constants
#define BB 2
#define CC 256
#define HH 64
#define WW 64
#define HWC (HH*WW)          // 4096
#define NQ (BB*HWC)          // 8192
#define NLVL 4
#define RAD 4
#define QT 16                // queries per tile
#define WS 112               // per-query w0 stride (100 used, padded)

// GEMM tiling: 128x128 block tile, 8 warps of 32x64, K chunks of 64, 3 stages
#define TM 128
#define TN 128
#define KC 64
#define NSTAGE 3
#define STAGE_BYTES ((TM+TN)*KC*2)           // 32 KB per stage
#define GEMM_SMEM_BYTES (NSTAGE*STAGE_BYTES + 1024)

// Merged pool+sample smem layout (dynamic)
#define SMP_SL1 0                            // __half [16][1024]  32 KB
#define SMP_SL2 32768                        // float  [16][256]   16 KB
#define SMP_SL3 49152                        // float  [16][64]     4 KB
#define SMP_SW  53248                        // float  [16][400]   25.6 KB
#define SAMPLE_SMEM_BYTES 78848

// Scratch (device globals; allocation-free rule)
__device__ __half g_f1h[BB*HWC*CC];          // (B, HW, C) fp16, 4 MB
__device__ __half g_f2h[BB*HWC*CC];          // (B, HW, C) fp16, 4 MB
__device__ __half g_f2l1[BB*1024*CC];        // pooled f2 (l1), 1 MB
__device__ __half g_c1[(size_t)NQ*32*32];    // corr lvl1 volume, 16.8 MB
__device__ __half g_w0[(size_t)NQ*WS];       // per-query l0 10x10 windows

__device__ __forceinline__ uint32_t smem_u32(const void* p) {
    uint32_t a;
    asm("{ .reg .u64 t; cvta.to.shared.u64 t, %1; cvt.u32.u64 %0, t; }"
        : "=r"(a) : "l"(p));
    return a;
}
__device__ __forceinline__ void cp16(uint32_t dst, const void* gsrc) {
    asm volatile("cp.async.cg.shared.global [%0], [%1], 16;"
                 :: "r"(dst), "l"(__cvta_generic_to_global(gsrc)) : "memory");
}
__device__ __forceinline__ void cp_commit() {
    asm volatile("cp.async.commit_group;" ::: "memory");
}
template <int N>
__device__ __forceinline__ void cp_wait() {
    asm volatile("cp.async.wait_group %0;" :: "n"(N) : "memory");
}

// ---------------------------------------------------------------------------
// Transpose both fmaps: (B,C,HW) fp32 -> (B,HW,C) fp16, one launch
// ---------------------------------------------------------------------------
__global__ void transpose_both_kernel(const float* __restrict__ in1,
                                      const float* __restrict__ in2) {
    __shared__ float tile[32][33];
    int z   = blockIdx.z;                // 0..2*BB-1
    int b   = z & (BB - 1);
    const float* in = (z < BB) ? in1 : in2;
    __half* outp    = (z < BB) ? g_f1h : g_f2h;
    int hw0 = blockIdx.x*32, c0 = blockIdx.y*32;
    int tx = threadIdx.x, ty = threadIdx.y;
#pragma unroll
    for (int i = 0; i < 32; i += 8)
        tile[ty + i][tx] = in[(b*CC + c0 + ty + i) * HWC + hw0 + tx];
    __syncthreads();
#pragma unroll
    for (int i = 0; i < 32; i += 8)
        outp[((size_t)b*HWC + hw0 + ty + i) * CC + c0 + tx] =
            __float2half_rn(tile[tx][ty + i]);
}

// ---------------------------------------------------------------------------
// Pool f2 features to level-1 grid: f2l1[b, y1*32+x1, c] = mean of 2x2 f2
// ---------------------------------------------------------------------------
__global__ void pool_f2_kernel() {
    int idx = blockIdx.x * blockDim.x + threadIdx.x;
    if (idx >= BB * 1024 * (CC/2)) return;
    int c2 = idx & 127;
    int j  = (idx >> 7) & 1023;
    int b  = idx >> 17;
    int y1 = j >> 5, x1 = j & 31;
    const __half2* base = (const __half2*)g_f2h + (size_t)b * HWC * (CC/2);
    float2 a  = __half22float2(base[((2*y1  )*64 + 2*x1  ) * 128 + c2]);
    float2 bb = __half22float2(base[((2*y1  )*64 + 2*x1+1) * 128 + c2]);
    float2 c  = __half22float2(base[((2*y1+1)*64 + 2*x1  ) * 128 + c2]);
    float2 d  = __half22float2(base[((2*y1+1)*64 + 2*x1+1) * 128 + c2]);
    ((__half2*)g_f2l1)[idx] =
        __floats2half2_rn(0.25f * (a.x + bb.x + c.x + d.x),
                          0.25f * (a.y + bb.y + c.y + d.y));
}

// ---------------------------------------------------------------------------
// Pipelined GEMM (mma.sync, 32x64 warp tiles, 3-stage cp.async):
// c1[b, i, j1] = <f1[i], f2l1[j1]> / 16, M=4096, N=1024, K=256.
// ---------------------------------------------------------------------------
__global__ __launch_bounds__(256, 2)
void gemm_l1_kernel() {
    extern __shared__ __align__(16) char dsm[];
    uint32_t raw = smem_u32(dsm);
    uint32_t sb  = (raw + 1023u) & ~1023u;
    char*    smp = dsm + (sb - raw);

    int tid = threadIdx.x;
    int lid = tid & 31;
    int w   = tid >> 5;
    int wm  = w & 3;                          // M group (4 x 32)
    int wn  = w >> 2;                         // N group (2 x 64)
    int b   = blockIdx.z;
    int i0  = blockIdx.y * TM;
    int j0  = blockIdx.x * TN;

    const uint4* gA = (const uint4*)(g_f1h  + ((size_t)(b*HWC  + i0)) * CC);
    const uint4* gB = (const uint4*)(g_f2l1 + ((size_t)(b*1024 + j0)) * CC);

    auto load_stage = [&](int st, int kc) {
        uint32_t sS = sb + st * STAGE_BYTES;
#pragma unroll
        for (int i = 0; i < 4; i++) {
            int idx = tid + i * 256;
            int r = idx >> 3, cl = idx & 7;
            uint32_t off = (uint32_t)r * 128u + (uint32_t)((cl ^ (r & 7)) << 4);
            cp16(sS + off, gA + r * 32 + kc * 8 + cl);
        }
#pragma unroll
        for (int i = 0; i < 4; i++) {
            int idx = tid + i * 256;
            int r = idx >> 3, cl = idx & 7;
            uint32_t off = (uint32_t)r * 128u + (uint32_t)((cl ^ (r & 7)) << 4);
            cp16(sS + TM*KC*2 + off, gB + r * 32 + kc * 8 + cl);
        }
        cp_commit();
    };

    float acc[2][8][4];
#pragma unroll
    for (int mi = 0; mi < 2; mi++)
#pragma unroll
        for (int j = 0; j < 8; j++)
#pragma unroll
            for (int u = 0; u < 4; u++) acc[mi][j][u] = 0.f;

    int m0 = wm * 32;
    int nb = wn * 64;
    int arow = m0 + (lid & 15);
    int acb  = lid >> 4;
    int brow = nb + (lid & 7) + ((lid >> 4) << 3);
    int bcb  = (lid >> 3) & 1;

    load_stage(0, 0);
    load_stage(1, 1);

#pragma unroll
    for (int kc = 0; kc < 4; kc++) {
        if (kc < 3) cp_wait<1>(); else cp_wait<0>();
        __syncthreads();
        if (kc < 2) load_stage((kc + 2) % NSTAGE, kc + 2);

        uint32_t sA = sb + (kc % NSTAGE) * STAGE_BYTES;
        uint32_t sB = sA + TM*KC*2;
#pragma unroll
        for (int ks = 0; ks < 4; ks++) {
            uint32_t a[2][4];
#pragma unroll
            for (int mi = 0; mi < 2; mi++) {
                int row = arow + mi * 16;
                int ch  = ks * 2 + acb;
                uint32_t addr = sA + (uint32_t)row * 128u
                              + (uint32_t)((ch ^ (row & 7)) << 4);
                asm volatile(
                    "ldmatrix.sync.aligned.m8n8.x4.shared.b16 {%0,%1,%2,%3}, [%4];"
                    : "=r"(a[mi][0]), "=r"(a[mi][1]), "=r"(a[mi][2]), "=r"(a[mi][3])
                    : "r"(addr));
            }
            uint32_t bf[4][4];
#pragma unroll
            for (int ng = 0; ng < 4; ng++) {
                int row = brow + ng * 16;
                int ch  = ks * 2 + bcb;
                uint32_t addr = sB + (uint32_t)row * 128u
                              + (uint32_t)((ch ^ (row & 7)) << 4);
                asm volatile(
                    "ldmatrix.sync.aligned.m8n8.x4.shared.b16 {%0,%1,%2,%3}, [%4];"
                    : "=r"(bf[ng][0]), "=r"(bf[ng][1]), "=r"(bf[ng][2]), "=r"(bf[ng][3])
                    : "r"(addr));
            }
#pragma unroll
            for (int mi = 0; mi < 2; mi++)
#pragma unroll
                for (int j = 0; j < 8; j++) {
                    int ng = j >> 1, pr = (j & 1) * 2;
                    asm volatile(
                        "mma.sync.aligned.m16n8k16.row.col.f32.f16.f16.f32 "
                        "{%0,%1,%2,%3}, {%4,%5,%6,%7}, {%8,%9}, {%0,%1,%2,%3};"
                        : "+f"(acc[mi][j][0]), "+f"(acc[mi][j][1]),
                          "+f"(acc[mi][j][2]), "+f"(acc[mi][j][3])
                        : "r"(a[mi][0]), "r"(a[mi][1]), "r"(a[mi][2]), "r"(a[mi][3]),
                          "r"(bf[ng][pr]), "r"(bf[ng][pr + 1]));
                }
        }
        __syncthreads();
    }

    // ---- epilogue: fragments -> smem tile (128x128 fp16) -> c1 ----
    {
        __half* epi = (__half*)smp;           // 32 KB, reuse stage 0
        const float s = 0.0625f;              // 1/sqrt(256)
#pragma unroll
        for (int mi = 0; mi < 2; mi++)
#pragma unroll
            for (int j = 0; j < 8; j++) {
                int n = nb + j * 8 + (lid & 3) * 2;
                int m = m0 + mi * 16 + (lid >> 2);
                *(__half2*)(epi + m * 128 + n) =
                    __floats2half2_rn(acc[mi][j][0] * s, acc[mi][j][1] * s);
                *(__half2*)(epi + (m + 8) * 128 + n) =
                    __floats2half2_rn(acc[mi][j][2] * s, acc[mi][j][3] * s);
            }
        __syncthreads();
        const uint4* ev = (const uint4*)epi;
#pragma unroll
        for (int it = 0; it < 8; it++) {
            int idx = tid + it * 256;         // 2048 uint4
            int r = idx >> 4, c = idx & 15;
            *(uint4*)(g_c1 + ((size_t)(b*HWC + i0 + r)) * 1024 + j0 + c * 8) =
                ev[idx];
        }
    }
}

// ---------------------------------------------------------------------------
// Direct level-0 window dots: w0[q][t] = <f1_q, f2[tap_t]> / 16 (0 if OOB).
// Grid (512, 2); block = 16 queries; 32 groups of 8 lanes.
// Coalesced chunk->lane mapping (iteration u -> chunk u*8+sub).
// fp16 pairwise chains (4-deep __hfma2) + fp32 accumulation per uint4.
// ---------------------------------------------------------------------------
__global__ __launch_bounds__(256)
void w0_sample_kernel(const float* __restrict__ coords) {
    int bidx = blockIdx.x;
    int b    = bidx >> 8;
    int hw0  = (bidx & 255) * QT;
    int t0   = blockIdx.y * 50;              // tap range [t0, t0+50)
    int tid  = threadIdx.x;
    int sub  = tid & 7;
    int grp  = tid >> 3;
    int q    = grp >> 1;
    int half = grp & 1;
    int n    = b * HWC + hw0 + q;

    // f1 chunks {u*8+sub} as half2 (16 regs), coalesced 128B per group
    __half2 rh1[16];
    {
        const uint4* p = (const uint4*)(g_f1h + (size_t)n * CC);
#pragma unroll
        for (int u = 0; u < 4; u++) {
            uint4 h8 = p[u * 8 + sub];
            rh1[u*4+0] = *(const __half2*)&h8.x;
            rh1[u*4+1] = *(const __half2*)&h8.y;
            rh1[u*4+2] = *(const __half2*)&h8.z;
            rh1[u*4+3] = *(const __half2*)&h8.w;
        }
    }
    float xq = coords[(b*2 + 0) * HWC + hw0 + q];
    float yq = coords[(b*2 + 1) * HWC + hw0 + q];
    int bx = (int)floorf(xq) - RAD;
    int by = (int)floorf(yq) - RAD;
    const __half* f2b = g_f2h + (size_t)b * HWC * CC;

#pragma unroll 5
    for (int t = t0 + half; t < t0 + 50; t += 2) {
        int ty = (t * 205) >> 11;            // /10
        int tx = t - ty * 10;
        int ix = bx + tx, iy = by + ty;
        float acc0 = 0.f, acc1 = 0.f;
        if (((unsigned)ix < 64u) & ((unsigned)iy < 64u)) {
            const uint4* p =
                (const uint4*)(f2b + ((size_t)(iy*64 + ix)) * CC);
#pragma unroll
            for (int u = 0; u < 4; u++) {
                uint4 h8 = p[u * 8 + sub];
                __half2 s = __hmul2(rh1[u*4+0], *(const __half2*)&h8.x);
                s = __hfma2(rh1[u*4+1], *(const __half2*)&h8.y, s);
                s = __hfma2(rh1[u*4+2], *(const __half2*)&h8.z, s);
                s = __hfma2(rh1[u*4+3], *(const __half2*)&h8.w, s);
                float2 f = __half22float2(s);
                acc0 += f.x;
                acc1 += f.y;
            }
        }
        float acc = acc0 + acc1;
        acc += __shfl_down_sync(0xffffffffu, acc, 4);
        acc += __shfl_down_sync(0xffffffffu, acc, 2);
        acc += __shfl_down_sync(0xffffffffu, acc, 1);
        if (sub == 0)
            g_w0[(size_t)n * WS + t] = __float2half_rn(acc * 0.0625f);
    }
}

// ---------------------------------------------------------------------------
// Merged pool+sample: block = 16 queries. l1 rows -> smem; l2/l3 pooled in
// smem (fp32); windows staged; 324 bilinear outputs/query. No divisions.
// ---------------------------------------------------------------------------
__global__ __launch_bounds__(256)
void pool_sample_kernel(const float* __restrict__ coords,
                        float* __restrict__ out) {
    extern __shared__ __align__(16) char sm[];
    __half* sl1 = (__half*)(sm + SMP_SL1);     // [16][1024]
    float*  sl2 = (float*) (sm + SMP_SL2);     // [16][256]
    float*  sl3 = (float*) (sm + SMP_SL3);     // [16][64]
    float*  sW  = (float*) (sm + SMP_SW);      // [16][400]
    __shared__ float sX[QT], sY[QT];

    int bidx = blockIdx.x;                     // 0..511
    int b    = bidx >> 8;
    int hw0  = (bidx & 255) * QT;
    int n0   = b * HWC + hw0;
    int tid  = threadIdx.x;

    if (tid < QT) {
        sX[tid] = coords[(b*2 + 0) * HWC + hw0 + tid];
        sY[tid] = coords[(b*2 + 1) * HWC + hw0 + tid];
    }

    // load 16 l1 rows (contiguous 32 KB)
    {
        const uint4* src = (const uint4*)(g_c1 + (size_t)n0 * 1024);
        uint4* dst = (uint4*)sl1;
#pragma unroll
        for (int i = 0; i < 8; i++) dst[tid + i*256] = src[tid + i*256];
    }
    __syncthreads();

    // l2 pool (fp32): 4096 cells
#pragma unroll
    for (int i = 0; i < 16; i++) {
        int c = tid + i*256;
        int q = c >> 8, r = c & 255;
        int y = r >> 4, x = r & 15;
        const __half* base = sl1 + q*1024 + (2*y)*32 + 2*x;
        float2 p0 = __half22float2(*(const __half2*)base);
        float2 p1 = __half22float2(*(const __half2*)(base + 32));
        sl2[c] = 0.25f * (p0.x + p0.y + p1.x + p1.y);
    }
    __syncthreads();

    // l3 pool: 1024 cells
#pragma unroll
    for (int i = 0; i < 4; i++) {
        int c = tid + i*256;
        int q = c >> 6, r = c & 63;
        int y = r >> 3, x = r & 7;
        const float* base = sl2 + q*256 + (2*y)*16 + 2*x;
        sl3[c] = 0.25f * (base[0] + base[1] + base[16] + base[17]);
    }
    __syncthreads();

    // stage windows: per level, 1600 = 16 q x 100 taps
#pragma unroll
    for (int l = 0; l < 4; l++) {
#pragma unroll
        for (int i = 0; i < 7; i++) {
            int idx = tid + i*256;
            if (idx < 1600) {
                int q  = (int)(((unsigned)idx * 5243u) >> 19);   // /100
                int t  = idx - q * 100;
                int ty = (int)(((unsigned)t * 205u) >> 11);      // /10
                int tx = t - ty * 10;
                float sc = 1.0f / (float)(1 << l);
                float xc = sX[q] * sc, yc = sY[q] * sc;
                int ix = (int)floorf(xc) - RAD + tx;
                int iy = (int)floorf(yc) - RAD + ty;
                int Wl = 64 >> l;
                float v = 0.f;
                if (ix >= 0 && ix < Wl && iy >= 0 && iy < Wl) {
                    if      (l == 0) v = __half2float(g_w0[(size_t)(n0+q)*WS + t]);
                    else if (l == 1) v = __half2float(sl1[q*1024 + iy*32 + ix]);
                    else if (l == 2) v = sl2[q*256 + iy*16 + ix];
                    else             v = sl3[q*64 + iy*8 + ix];
                }
                sW[q*400 + l*100 + t] = v;
            }
        }
    }
    __syncthreads();

    // outputs: per level, 1296 = 81 taps x 16 q
#pragma unroll
    for (int l = 0; l < 4; l++) {
        float sc = 1.0f / (float)(1 << l);
#pragma unroll
        for (int i = 0; i < 6; i++) {
            int idx = tid + i*256;
            if (idx < 1296) {
                int k  = idx >> 4;
                int qq = idx & 15;
                int cx = (int)(((unsigned)k * 57u) >> 9);        // /9
                int ry = k - cx * 9;
                float xq = sX[qq] * sc;
                float yq = sY[qq] * sc;
                float fx = xq - floorf(xq);
                float fy = yq - floorf(yq);
                const float* W = sW + qq*400 + l*100;
                float v00 = W[ ry      * 10 + cx    ];
                float v01 = W[ ry      * 10 + cx + 1];
                float v10 = W[(ry + 1) * 10 + cx    ];
                float v11 = W[(ry + 1) * 10 + cx + 1];
                float v = (1.f - fy) * ((1.f - fx) * v00 + fx * v01)
                        +        fy  * ((1.f - fx) * v10 + fx * v11);
                out[((size_t)(b * 324 + l * 81 + k)) * HWC + hw0 + qq] = v;
            }
        }
    }
}

// ---------------------------------------------------------------------------
extern "C" void kernel_launch(void* const* d_in, const int* in_sizes, int n_in,
                              void* d_out, int out_size) {
    const float* fmap1  = (const float*)d_in[0];
    const float* fmap2  = (const float*)d_in[1];
    const float* coords = (const float*)d_in[2];
    float* out = (float*)d_out;

    cudaFuncSetAttribute(gemm_l1_kernel,
                         cudaFuncAttributeMaxDynamicSharedMemorySize,
                         GEMM_SMEM_BYTES);
    cudaFuncSetAttribute(pool_sample_kernel,
                         cudaFuncAttributeMaxDynamicSharedMemorySize,
                         SAMPLE_SMEM_BYTES);

    dim3 tgrid(HWC / 32, CC / 32, 2*BB);
    dim3 tblk(32, 8);
    transpose_both_kernel<<<tgrid, tblk>>>(fmap1, fmap2);

    pool_f2_kernel<<<(BB*1024*(CC/2) + 255) / 256, 256>>>();

    dim3 ggrid(1024 / TN, HWC / TM, BB);  // (8, 32, 2)
    gemm_l1_kernel<<<ggrid, 256, GEMM_SMEM_BYTES>>>();

    dim3 wgrid(NQ / QT, 2);               // (512, 2) — 50 taps per block
    w0_sample_kernel<<<wgrid, 256>>>(coords);

    pool_sample_kernel<<<NQ / QT, 256, SAMPLE_SMEM_BYTES>>>(coords, out);
}

// round 16
// speedup vs baseline: 1.5656x; 1.1199x over previous
#include <cuda_runtime.h>
#include <cuda_fp16.h>
#include <cstdint>

// Problem constants
#define BB 2
#define CC 256
#define HH 64
#define WW 64
#define HWC (HH*WW)          // 4096
#define NQ (BB*HWC)          // 8192
#define NLVL 4
#define RAD 4
#define QT 16                // queries per tile
#define WS 112               // per-query w0 stride (100 used, padded)

// GEMM tiling: 128x128 block tile, 8 warps of 32x64, K chunks of 64, 3 stages
#define TM 128
#define TN 128
#define KC 64
#define NSTAGE 3
#define STAGE_BYTES ((TM+TN)*KC*2)           // 32 KB per stage
#define GEMM_SMEM_BYTES (NSTAGE*STAGE_BYTES + 1024)

// Merged pool+sample smem layout (dynamic)
#define SMP_SL1 0                            // __half [16][1024]  32 KB
#define SMP_SL2 32768                        // float  [16][256]   16 KB
#define SMP_SL3 49152                        // float  [16][64]     4 KB
#define SMP_SW  53248                        // float  [16][400]   25.6 KB
#define SAMPLE_SMEM_BYTES 78848

// Scratch (device globals; allocation-free rule)
__device__ __half g_f1h[BB*HWC*CC];          // (B, HW, C) fp16, 4 MB
__device__ __half g_f2h[BB*HWC*CC];          // (B, HW, C) fp16, 4 MB
__device__ __half g_f2l1[BB*1024*CC];        // pooled f2 (l1), 1 MB
__device__ __half g_c1[(size_t)NQ*32*32];    // corr lvl1 volume, 16.8 MB
__device__ __half g_w0[(size_t)NQ*WS];       // per-query l0 10x10 windows

__device__ __forceinline__ uint32_t smem_u32(const void* p) {
    uint32_t a;
    asm("{ .reg .u64 t; cvta.to.shared.u64 t, %1; cvt.u32.u64 %0, t; }"
        : "=r"(a) : "l"(p));
    return a;
}
__device__ __forceinline__ void cp16(uint32_t dst, const void* gsrc) {
    asm volatile("cp.async.cg.shared.global [%0], [%1], 16;"
                 :: "r"(dst), "l"(__cvta_generic_to_global(gsrc)) : "memory");
}
__device__ __forceinline__ void cp_commit() {
    asm volatile("cp.async.commit_group;" ::: "memory");
}
template <int N>
__device__ __forceinline__ void cp_wait() {
    asm volatile("cp.async.wait_group %0;" :: "n"(N) : "memory");
}

// ---------------------------------------------------------------------------
// Transpose both fmaps: (B,C,HW) fp32 -> (B,HW,C) fp16, one launch
// ---------------------------------------------------------------------------
__global__ void transpose_both_kernel(const float* __restrict__ in1,
                                      const float* __restrict__ in2) {
    __shared__ float tile[32][33];
    int z   = blockIdx.z;                // 0..2*BB-1
    int b   = z & (BB - 1);
    const float* in = (z < BB) ? in1 : in2;
    __half* outp    = (z < BB) ? g_f1h : g_f2h;
    int hw0 = blockIdx.x*32, c0 = blockIdx.y*32;
    int tx = threadIdx.x, ty = threadIdx.y;
#pragma unroll
    for (int i = 0; i < 32; i += 8)
        tile[ty + i][tx] = in[(b*CC + c0 + ty + i) * HWC + hw0 + tx];
    __syncthreads();
#pragma unroll
    for (int i = 0; i < 32; i += 8)
        outp[((size_t)b*HWC + hw0 + ty + i) * CC + c0 + tx] =
            __float2half_rn(tile[tx][ty + i]);
}

// ---------------------------------------------------------------------------
// Pool f2 features to level-1 grid: f2l1[b, y1*32+x1, c] = mean of 2x2 f2
// ---------------------------------------------------------------------------
__global__ void pool_f2_kernel() {
    int idx = blockIdx.x * blockDim.x + threadIdx.x;
    if (idx >= BB * 1024 * (CC/2)) return;
    int c2 = idx & 127;
    int j  = (idx >> 7) & 1023;
    int b  = idx >> 17;
    int y1 = j >> 5, x1 = j & 31;
    const __half2* base = (const __half2*)g_f2h + (size_t)b * HWC * (CC/2);
    float2 a  = __half22float2(base[((2*y1  )*64 + 2*x1  ) * 128 + c2]);
    float2 bb = __half22float2(base[((2*y1  )*64 + 2*x1+1) * 128 + c2]);
    float2 c  = __half22float2(base[((2*y1+1)*64 + 2*x1  ) * 128 + c2]);
    float2 d  = __half22float2(base[((2*y1+1)*64 + 2*x1+1) * 128 + c2]);
    ((__half2*)g_f2l1)[idx] =
        __floats2half2_rn(0.25f * (a.x + bb.x + c.x + d.x),
                          0.25f * (a.y + bb.y + c.y + d.y));
}

// ---------------------------------------------------------------------------
// Pipelined GEMM (mma.sync, 32x64 warp tiles, 3-stage cp.async):
// c1[b, i, j1] = <f1[i], f2l1[j1]> / 16, M=4096, N=1024, K=256.
// ---------------------------------------------------------------------------
__global__ __launch_bounds__(256, 2)
void gemm_l1_kernel() {
    extern __shared__ __align__(16) char dsm[];
    uint32_t raw = smem_u32(dsm);
    uint32_t sb  = (raw + 1023u) & ~1023u;
    char*    smp = dsm + (sb - raw);

    int tid = threadIdx.x;
    int lid = tid & 31;
    int w   = tid >> 5;
    int wm  = w & 3;                          // M group (4 x 32)
    int wn  = w >> 2;                         // N group (2 x 64)
    int b   = blockIdx.z;
    int i0  = blockIdx.y * TM;
    int j0  = blockIdx.x * TN;

    const uint4* gA = (const uint4*)(g_f1h  + ((size_t)(b*HWC  + i0)) * CC);
    const uint4* gB = (const uint4*)(g_f2l1 + ((size_t)(b*1024 + j0)) * CC);

    auto load_stage = [&](int st, int kc) {
        uint32_t sS = sb + st * STAGE_BYTES;
#pragma unroll
        for (int i = 0; i < 4; i++) {
            int idx = tid + i * 256;
            int r = idx >> 3, cl = idx & 7;
            uint32_t off = (uint32_t)r * 128u + (uint32_t)((cl ^ (r & 7)) << 4);
            cp16(sS + off, gA + r * 32 + kc * 8 + cl);
        }
#pragma unroll
        for (int i = 0; i < 4; i++) {
            int idx = tid + i * 256;
            int r = idx >> 3, cl = idx & 7;
            uint32_t off = (uint32_t)r * 128u + (uint32_t)((cl ^ (r & 7)) << 4);
            cp16(sS + TM*KC*2 + off, gB + r * 32 + kc * 8 + cl);
        }
        cp_commit();
    };

    float acc[2][8][4];
#pragma unroll
    for (int mi = 0; mi < 2; mi++)
#pragma unroll
        for (int j = 0; j < 8; j++)
#pragma unroll
            for (int u = 0; u < 4; u++) acc[mi][j][u] = 0.f;

    int m0 = wm * 32;
    int nb = wn * 64;
    int arow = m0 + (lid & 15);
    int acb  = lid >> 4;
    int brow = nb + (lid & 7) + ((lid >> 4) << 3);
    int bcb  = (lid >> 3) & 1;

    load_stage(0, 0);
    load_stage(1, 1);

#pragma unroll
    for (int kc = 0; kc < 4; kc++) {
        if (kc < 3) cp_wait<1>(); else cp_wait<0>();
        __syncthreads();
        if (kc < 2) load_stage((kc + 2) % NSTAGE, kc + 2);

        uint32_t sA = sb + (kc % NSTAGE) * STAGE_BYTES;
        uint32_t sB = sA + TM*KC*2;
#pragma unroll
        for (int ks = 0; ks < 4; ks++) {
            uint32_t a[2][4];
#pragma unroll
            for (int mi = 0; mi < 2; mi++) {
                int row = arow + mi * 16;
                int ch  = ks * 2 + acb;
                uint32_t addr = sA + (uint32_t)row * 128u
                              + (uint32_t)((ch ^ (row & 7)) << 4);
                asm volatile(
                    "ldmatrix.sync.aligned.m8n8.x4.shared.b16 {%0,%1,%2,%3}, [%4];"
                    : "=r"(a[mi][0]), "=r"(a[mi][1]), "=r"(a[mi][2]), "=r"(a[mi][3])
                    : "r"(addr));
            }
            uint32_t bf[4][4];
#pragma unroll
            for (int ng = 0; ng < 4; ng++) {
                int row = brow + ng * 16;
                int ch  = ks * 2 + bcb;
                uint32_t addr = sB + (uint32_t)row * 128u
                              + (uint32_t)((ch ^ (row & 7)) << 4);
                asm volatile(
                    "ldmatrix.sync.aligned.m8n8.x4.shared.b16 {%0,%1,%2,%3}, [%4];"
                    : "=r"(bf[ng][0]), "=r"(bf[ng][1]), "=r"(bf[ng][2]), "=r"(bf[ng][3])
                    : "r"(addr));
            }
#pragma unroll
            for (int mi = 0; mi < 2; mi++)
#pragma unroll
                for (int j = 0; j < 8; j++) {
                    int ng = j >> 1, pr = (j & 1) * 2;
                    asm volatile(
                        "mma.sync.aligned.m16n8k16.row.col.f32.f16.f16.f32 "
                        "{%0,%1,%2,%3}, {%4,%5,%6,%7}, {%8,%9}, {%0,%1,%2,%3};"
                        : "+f"(acc[mi][j][0]), "+f"(acc[mi][j][1]),
                          "+f"(acc[mi][j][2]), "+f"(acc[mi][j][3])
                        : "r"(a[mi][0]), "r"(a[mi][1]), "r"(a[mi][2]), "r"(a[mi][3]),
                          "r"(bf[ng][pr]), "r"(bf[ng][pr + 1]));
                }
        }
        __syncthreads();
    }

    // ---- epilogue: fragments -> smem tile (128x128 fp16) -> c1 ----
    {
        __half* epi = (__half*)smp;           // 32 KB, reuse stage 0
        const float s = 0.0625f;              // 1/sqrt(256)
#pragma unroll
        for (int mi = 0; mi < 2; mi++)
#pragma unroll
            for (int j = 0; j < 8; j++) {
                int n = nb + j * 8 + (lid & 3) * 2;
                int m = m0 + mi * 16 + (lid >> 2);
                *(__half2*)(epi + m * 128 + n) =
                    __floats2half2_rn(acc[mi][j][0] * s, acc[mi][j][1] * s);
                *(__half2*)(epi + (m + 8) * 128 + n) =
                    __floats2half2_rn(acc[mi][j][2] * s, acc[mi][j][3] * s);
            }
        __syncthreads();
        const uint4* ev = (const uint4*)epi;
#pragma unroll
        for (int it = 0; it < 8; it++) {
            int idx = tid + it * 256;         // 2048 uint4
            int r = idx >> 4, c = idx & 15;
            *(uint4*)(g_c1 + ((size_t)(b*HWC + i0 + r)) * 1024 + j0 + c * 8) =
                ev[idx];
        }
    }
}

// ---------------------------------------------------------------------------
// Direct level-0 window dots: w0[q][t] = <f1_q, f2[tap_t]> / 16 (0 if OOB).
// Grid (512, 2); block = 16 queries; 32 groups of 8 lanes.
// Coalesced chunk->lane mapping; fp16 pairwise HFMA2 chains + fp32 accum.
// ---------------------------------------------------------------------------
__global__ __launch_bounds__(256)
void w0_sample_kernel(const float* __restrict__ coords) {
    int bidx = blockIdx.x;
    int b    = bidx >> 8;
    int hw0  = (bidx & 255) * QT;
    int t0   = blockIdx.y * 50;              // tap range [t0, t0+50)
    int tid  = threadIdx.x;
    int sub  = tid & 7;
    int grp  = tid >> 3;
    int q    = grp >> 1;
    int half = grp & 1;
    int n    = b * HWC + hw0 + q;

    __half2 rh1[16];
    {
        const uint4* p = (const uint4*)(g_f1h + (size_t)n * CC);
#pragma unroll
        for (int u = 0; u < 4; u++) {
            uint4 h8 = p[u * 8 + sub];
            rh1[u*4+0] = *(const __half2*)&h8.x;
            rh1[u*4+1] = *(const __half2*)&h8.y;
            rh1[u*4+2] = *(const __half2*)&h8.z;
            rh1[u*4+3] = *(const __half2*)&h8.w;
        }
    }
    float xq = coords[(b*2 + 0) * HWC + hw0 + q];
    float yq = coords[(b*2 + 1) * HWC + hw0 + q];
    int bx = (int)floorf(xq) - RAD;
    int by = (int)floorf(yq) - RAD;
    const __half* f2b = g_f2h + (size_t)b * HWC * CC;

#pragma unroll 5
    for (int t = t0 + half; t < t0 + 50; t += 2) {
        int ty = (t * 205) >> 11;            // /10
        int tx = t - ty * 10;
        int ix = bx + tx, iy = by + ty;
        float acc0 = 0.f, acc1 = 0.f;
        if (((unsigned)ix < 64u) & ((unsigned)iy < 64u)) {
            const uint4* p =
                (const uint4*)(f2b + ((size_t)(iy*64 + ix)) * CC);
#pragma unroll
            for (int u = 0; u < 4; u++) {
                uint4 h8 = p[u * 8 + sub];
                __half2 s = __hmul2(rh1[u*4+0], *(const __half2*)&h8.x);
                s = __hfma2(rh1[u*4+1], *(const __half2*)&h8.y, s);
                s = __hfma2(rh1[u*4+2], *(const __half2*)&h8.z, s);
                s = __hfma2(rh1[u*4+3], *(const __half2*)&h8.w, s);
                float2 f = __half22float2(s);
                acc0 += f.x;
                acc1 += f.y;
            }
        }
        float acc = acc0 + acc1;
        acc += __shfl_down_sync(0xffffffffu, acc, 4);
        acc += __shfl_down_sync(0xffffffffu, acc, 2);
        acc += __shfl_down_sync(0xffffffffu, acc, 1);
        if (sub == 0)
            g_w0[(size_t)n * WS + t] = __float2half_rn(acc * 0.0625f);
    }
}

// ---------------------------------------------------------------------------
// Merged pool+sample: block = 16 queries. l1 rows -> smem; l2/l3 pooled in
// smem (fp32); windows staged; 324 bilinear outputs/query. No divisions.
// ---------------------------------------------------------------------------
__global__ __launch_bounds__(256)
void pool_sample_kernel(const float* __restrict__ coords,
                        float* __restrict__ out) {
    extern __shared__ __align__(16) char sm[];
    __half* sl1 = (__half*)(sm + SMP_SL1);     // [16][1024]
    float*  sl2 = (float*) (sm + SMP_SL2);     // [16][256]
    float*  sl3 = (float*) (sm + SMP_SL3);     // [16][64]
    float*  sW  = (float*) (sm + SMP_SW);      // [16][400]
    __shared__ float sX[QT], sY[QT];

    int bidx = blockIdx.x;                     // 0..511
    int b    = bidx >> 8;
    int hw0  = (bidx & 255) * QT;
    int n0   = b * HWC + hw0;
    int tid  = threadIdx.x;

    if (tid < QT) {
        sX[tid] = coords[(b*2 + 0) * HWC + hw0 + tid];
        sY[tid] = coords[(b*2 + 1) * HWC + hw0 + tid];
    }

    // load 16 l1 rows (contiguous 32 KB)
    {
        const uint4* src = (const uint4*)(g_c1 + (size_t)n0 * 1024);
        uint4* dst = (uint4*)sl1;
#pragma unroll
        for (int i = 0; i < 8; i++) dst[tid + i*256] = src[tid + i*256];
    }
    __syncthreads();

    // l2 pool (fp32): 4096 cells
#pragma unroll
    for (int i = 0; i < 16; i++) {
        int c = tid + i*256;
        int q = c >> 8, r = c & 255;
        int y = r >> 4, x = r & 15;
        const __half* base = sl1 + q*1024 + (2*y)*32 + 2*x;
        float2 p0 = __half22float2(*(const __half2*)base);
        float2 p1 = __half22float2(*(const __half2*)(base + 32));
        sl2[c] = 0.25f * (p0.x + p0.y + p1.x + p1.y);
    }
    __syncthreads();

    // l3 pool: 1024 cells
#pragma unroll
    for (int i = 0; i < 4; i++) {
        int c = tid + i*256;
        int q = c >> 6, r = c & 63;
        int y = r >> 3, x = r & 7;
        const float* base = sl2 + q*256 + (2*y)*16 + 2*x;
        sl3[c] = 0.25f * (base[0] + base[1] + base[16] + base[17]);
    }
    __syncthreads();

    // stage windows: per level, 1600 = 16 q x 100 taps
#pragma unroll
    for (int l = 0; l < 4; l++) {
#pragma unroll
        for (int i = 0; i < 7; i++) {
            int idx = tid + i*256;
            if (idx < 1600) {
                int q  = (int)(((unsigned)idx * 5243u) >> 19);   // /100
                int t  = idx - q * 100;
                int ty = (int)(((unsigned)t * 205u) >> 11);      // /10
                int tx = t - ty * 10;
                float sc = 1.0f / (float)(1 << l);
                float xc = sX[q] * sc, yc = sY[q] * sc;
                int ix = (int)floorf(xc) - RAD + tx;
                int iy = (int)floorf(yc) - RAD + ty;
                int Wl = 64 >> l;
                float v = 0.f;
                if (ix >= 0 && ix < Wl && iy >= 0 && iy < Wl) {
                    if      (l == 0) v = __half2float(g_w0[(size_t)(n0+q)*WS + t]);
                    else if (l == 1) v = __half2float(sl1[q*1024 + iy*32 + ix]);
                    else if (l == 2) v = sl2[q*256 + iy*16 + ix];
                    else             v = sl3[q*64 + iy*8 + ix];
                }
                sW[q*400 + l*100 + t] = v;
            }
        }
    }
    __syncthreads();

    // outputs: per level, 1296 = 81 taps x 16 q
#pragma unroll
    for (int l = 0; l < 4; l++) {
        float sc = 1.0f / (float)(1 << l);
#pragma unroll
        for (int i = 0; i < 6; i++) {
            int idx = tid + i*256;
            if (idx < 1296) {
                int k  = idx >> 4;
                int qq = idx & 15;
                int cx = (int)(((unsigned)k * 57u) >> 9);        // /9
                int ry = k - cx * 9;
                float xq = sX[qq] * sc;
                float yq = sY[qq] * sc;
                float fx = xq - floorf(xq);
                float fy = yq - floorf(yq);
                const float* W = sW + qq*400 + l*100;
                float v00 = W[ ry      * 10 + cx    ];
                float v01 = W[ ry      * 10 + cx + 1];
                float v10 = W[(ry + 1) * 10 + cx    ];
                float v11 = W[(ry + 1) * 10 + cx + 1];
                float v = (1.f - fy) * ((1.f - fx) * v00 + fx * v01)
                        +        fy  * ((1.f - fx) * v10 + fx * v11);
                out[((size_t)(b * 324 + l * 81 + k)) * HWC + hw0 + qq] = v;
            }
        }
    }
}

// ---------------------------------------------------------------------------
extern "C" void kernel_launch(void* const* d_in, const int* in_sizes, int n_in,
                              void* d_out, int out_size) {
    const float* fmap1  = (const float*)d_in[0];
    const float* fmap2  = (const float*)d_in[1];
    const float* coords = (const float*)d_in[2];
    float* out = (float*)d_out;

    // One-time side stream + events (host-side objects; no device memory).
    static cudaStream_t s_side = nullptr;
    static cudaEvent_t  s_fork = nullptr, s_join = nullptr;
    if (s_side == nullptr) {
        cudaStreamCreateWithFlags(&s_side, cudaStreamNonBlocking);
        cudaEventCreateWithFlags(&s_fork, cudaEventDisableTiming);
        cudaEventCreateWithFlags(&s_join, cudaEventDisableTiming);
        cudaFuncSetAttribute(gemm_l1_kernel,
                             cudaFuncAttributeMaxDynamicSharedMemorySize,
                             GEMM_SMEM_BYTES);
        cudaFuncSetAttribute(pool_sample_kernel,
                             cudaFuncAttributeMaxDynamicSharedMemorySize,
                             SAMPLE_SMEM_BYTES);
    }

    dim3 tgrid(HWC / 32, CC / 32, 2*BB);
    dim3 tblk(32, 8);
    transpose_both_kernel<<<tgrid, tblk>>>(fmap1, fmap2);

    // Fork: w0_sample on side stream (needs only transposed features),
    // pool_f2 + gemm_l1 stay on the main stream.
    cudaEventRecord(s_fork, 0);
    cudaStreamWaitEvent(s_side, s_fork, 0);

    dim3 wgrid(NQ / QT, 2);               // (512, 2) — 50 taps per block
    w0_sample_kernel<<<wgrid, 256, 0, s_side>>>(coords);
    cudaEventRecord(s_join, s_side);

    pool_f2_kernel<<<(BB*1024*(CC/2) + 255) / 256, 256>>>();
    dim3 ggrid(1024 / TN, HWC / TM, BB);  // (8, 32, 2)
    gemm_l1_kernel<<<ggrid, 256, GEMM_SMEM_BYTES>>>();

    // Join: pool_sample needs both c1 (main) and w0 (side).
    cudaStreamWaitEvent(0, s_join, 0);
    pool_sample_kernel<<<NQ / QT, 256, SAMPLE_SMEM_BYTES>>>(coords, out);
}

// round 17
// speedup vs baseline: 1.6252x; 1.0381x over previous
#include <cuda_runtime.h>
#include <cuda_fp16.h>
#include <cstdint>

// Problem constants
#define BB 2
#define CC 256
#define HH 64
#define WW 64
#define HWC (HH*WW)          // 4096
#define NQ (BB*HWC)          // 8192
#define NLVL 4
#define RAD 4
#define QT 16                // queries per tile

// GEMM tiling: 128x128 block tile, 8 warps of 32x64, K chunks of 64, 3 stages
#define TM 128
#define TN 128
#define KC 64
#define NSTAGE 3
#define STAGE_BYTES ((TM+TN)*KC*2)           // 32 KB per stage
#define GEMM_SMEM_BYTES (NSTAGE*STAGE_BYTES + 1024)

// Merged pool+sample smem layout (dynamic) — levels 1..3 only
#define SMP_SL1 0                            // __half [16][1024]  32 KB
#define SMP_SL2 32768                        // float  [16][256]   16 KB
#define SMP_SL3 49152                        // float  [16][64]     4 KB
#define SMP_SW  53248                        // float  [16][304]   19.5 KB
#define SAMPLE_SMEM_BYTES (53248 + 16*304*4)

// Scratch (device globals; allocation-free rule)
__device__ __half g_f1h[BB*HWC*CC];          // (B, HW, C) fp16, 4 MB
__device__ __half g_f2h[BB*HWC*CC];          // (B, HW, C) fp16, 4 MB
__device__ __half g_f2l1[BB*1024*CC];        // pooled f2 (l1), 1 MB
__device__ __half g_c1[(size_t)NQ*32*32];    // corr lvl1 volume, 16.8 MB

__device__ __forceinline__ uint32_t smem_u32(const void* p) {
    uint32_t a;
    asm("{ .reg .u64 t; cvta.to.shared.u64 t, %1; cvt.u32.u64 %0, t; }"
        : "=r"(a) : "l"(p));
    return a;
}
__device__ __forceinline__ void cp16(uint32_t dst, const void* gsrc) {
    asm volatile("cp.async.cg.shared.global [%0], [%1], 16;"
                 :: "r"(dst), "l"(__cvta_generic_to_global(gsrc)) : "memory");
}
__device__ __forceinline__ void cp_commit() {
    asm volatile("cp.async.commit_group;" ::: "memory");
}
template <int N>
__device__ __forceinline__ void cp_wait() {
    asm volatile("cp.async.wait_group %0;" :: "n"(N) : "memory");
}

// ---------------------------------------------------------------------------
// Transpose both fmaps: (B,C,HW) fp32 -> (B,HW,C) fp16, one launch
// ---------------------------------------------------------------------------
__global__ void transpose_both_kernel(const float* __restrict__ in1,
                                      const float* __restrict__ in2) {
    __shared__ float tile[32][33];
    int z   = blockIdx.z;                // 0..2*BB-1
    int b   = z & (BB - 1);
    const float* in = (z < BB) ? in1 : in2;
    __half* outp    = (z < BB) ? g_f1h : g_f2h;
    int hw0 = blockIdx.x*32, c0 = blockIdx.y*32;
    int tx = threadIdx.x, ty = threadIdx.y;
#pragma unroll
    for (int i = 0; i < 32; i += 8)
        tile[ty + i][tx] = in[(b*CC + c0 + ty + i) * HWC + hw0 + tx];
    __syncthreads();
#pragma unroll
    for (int i = 0; i < 32; i += 8)
        outp[((size_t)b*HWC + hw0 + ty + i) * CC + c0 + tx] =
            __float2half_rn(tile[tx][ty + i]);
}

// ---------------------------------------------------------------------------
// Pool f2 features to level-1 grid: f2l1[b, y1*32+x1, c] = mean of 2x2 f2
// ---------------------------------------------------------------------------
__global__ void pool_f2_kernel() {
    int idx = blockIdx.x * blockDim.x + threadIdx.x;
    if (idx >= BB * 1024 * (CC/2)) return;
    int c2 = idx & 127;
    int j  = (idx >> 7) & 1023;
    int b  = idx >> 17;
    int y1 = j >> 5, x1 = j & 31;
    const __half2* base = (const __half2*)g_f2h + (size_t)b * HWC * (CC/2);
    float2 a  = __half22float2(base[((2*y1  )*64 + 2*x1  ) * 128 + c2]);
    float2 bb = __half22float2(base[((2*y1  )*64 + 2*x1+1) * 128 + c2]);
    float2 c  = __half22float2(base[((2*y1+1)*64 + 2*x1  ) * 128 + c2]);
    float2 d  = __half22float2(base[((2*y1+1)*64 + 2*x1+1) * 128 + c2]);
    ((__half2*)g_f2l1)[idx] =
        __floats2half2_rn(0.25f * (a.x + bb.x + c.x + d.x),
                          0.25f * (a.y + bb.y + c.y + d.y));
}

// ---------------------------------------------------------------------------
// Pipelined GEMM (mma.sync, 32x64 warp tiles, 3-stage cp.async):
// c1[b, i, j1] = <f1[i], f2l1[j1]> / 16, M=4096, N=1024, K=256.
// ---------------------------------------------------------------------------
__global__ __launch_bounds__(256, 2)
void gemm_l1_kernel() {
    extern __shared__ __align__(16) char dsm[];
    uint32_t raw = smem_u32(dsm);
    uint32_t sb  = (raw + 1023u) & ~1023u;
    char*    smp = dsm + (sb - raw);

    int tid = threadIdx.x;
    int lid = tid & 31;
    int w   = tid >> 5;
    int wm  = w & 3;                          // M group (4 x 32)
    int wn  = w >> 2;                         // N group (2 x 64)
    int b   = blockIdx.z;
    int i0  = blockIdx.y * TM;
    int j0  = blockIdx.x * TN;

    const uint4* gA = (const uint4*)(g_f1h  + ((size_t)(b*HWC  + i0)) * CC);
    const uint4* gB = (const uint4*)(g_f2l1 + ((size_t)(b*1024 + j0)) * CC);

    auto load_stage = [&](int st, int kc) {
        uint32_t sS = sb + st * STAGE_BYTES;
#pragma unroll
        for (int i = 0; i < 4; i++) {
            int idx = tid + i * 256;
            int r = idx >> 3, cl = idx & 7;
            uint32_t off = (uint32_t)r * 128u + (uint32_t)((cl ^ (r & 7)) << 4);
            cp16(sS + off, gA + r * 32 + kc * 8 + cl);
        }
#pragma unroll
        for (int i = 0; i < 4; i++) {
            int idx = tid + i * 256;
            int r = idx >> 3, cl = idx & 7;
            uint32_t off = (uint32_t)r * 128u + (uint32_t)((cl ^ (r & 7)) << 4);
            cp16(sS + TM*KC*2 + off, gB + r * 32 + kc * 8 + cl);
        }
        cp_commit();
    };

    float acc[2][8][4];
#pragma unroll
    for (int mi = 0; mi < 2; mi++)
#pragma unroll
        for (int j = 0; j < 8; j++)
#pragma unroll
            for (int u = 0; u < 4; u++) acc[mi][j][u] = 0.f;

    int m0 = wm * 32;
    int nb = wn * 64;
    int arow = m0 + (lid & 15);
    int acb  = lid >> 4;
    int brow = nb + (lid & 7) + ((lid >> 4) << 3);
    int bcb  = (lid >> 3) & 1;

    load_stage(0, 0);
    load_stage(1, 1);

#pragma unroll
    for (int kc = 0; kc < 4; kc++) {
        if (kc < 3) cp_wait<1>(); else cp_wait<0>();
        __syncthreads();
        if (kc < 2) load_stage((kc + 2) % NSTAGE, kc + 2);

        uint32_t sA = sb + (kc % NSTAGE) * STAGE_BYTES;
        uint32_t sB = sA + TM*KC*2;
#pragma unroll
        for (int ks = 0; ks < 4; ks++) {
            uint32_t a[2][4];
#pragma unroll
            for (int mi = 0; mi < 2; mi++) {
                int row = arow + mi * 16;
                int ch  = ks * 2 + acb;
                uint32_t addr = sA + (uint32_t)row * 128u
                              + (uint32_t)((ch ^ (row & 7)) << 4);
                asm volatile(
                    "ldmatrix.sync.aligned.m8n8.x4.shared.b16 {%0,%1,%2,%3}, [%4];"
                    : "=r"(a[mi][0]), "=r"(a[mi][1]), "=r"(a[mi][2]), "=r"(a[mi][3])
                    : "r"(addr));
            }
            uint32_t bf[4][4];
#pragma unroll
            for (int ng = 0; ng < 4; ng++) {
                int row = brow + ng * 16;
                int ch  = ks * 2 + bcb;
                uint32_t addr = sB + (uint32_t)row * 128u
                              + (uint32_t)((ch ^ (row & 7)) << 4);
                asm volatile(
                    "ldmatrix.sync.aligned.m8n8.x4.shared.b16 {%0,%1,%2,%3}, [%4];"
                    : "=r"(bf[ng][0]), "=r"(bf[ng][1]), "=r"(bf[ng][2]), "=r"(bf[ng][3])
                    : "r"(addr));
            }
#pragma unroll
            for (int mi = 0; mi < 2; mi++)
#pragma unroll
                for (int j = 0; j < 8; j++) {
                    int ng = j >> 1, pr = (j & 1) * 2;
                    asm volatile(
                        "mma.sync.aligned.m16n8k16.row.col.f32.f16.f16.f32 "
                        "{%0,%1,%2,%3}, {%4,%5,%6,%7}, {%8,%9}, {%0,%1,%2,%3};"
                        : "+f"(acc[mi][j][0]), "+f"(acc[mi][j][1]),
                          "+f"(acc[mi][j][2]), "+f"(acc[mi][j][3])
                        : "r"(a[mi][0]), "r"(a[mi][1]), "r"(a[mi][2]), "r"(a[mi][3]),
                          "r"(bf[ng][pr]), "r"(bf[ng][pr + 1]));
                }
        }
        __syncthreads();
    }

    // ---- epilogue: fragments -> smem tile (128x128 fp16) -> c1 ----
    {
        __half* epi = (__half*)smp;           // 32 KB, reuse stage 0
        const float s = 0.0625f;              // 1/sqrt(256)
#pragma unroll
        for (int mi = 0; mi < 2; mi++)
#pragma unroll
            for (int j = 0; j < 8; j++) {
                int n = nb + j * 8 + (lid & 3) * 2;
                int m = m0 + mi * 16 + (lid >> 2);
                *(__half2*)(epi + m * 128 + n) =
                    __floats2half2_rn(acc[mi][j][0] * s, acc[mi][j][1] * s);
                *(__half2*)(epi + (m + 8) * 128 + n) =
                    __floats2half2_rn(acc[mi][j][2] * s, acc[mi][j][3] * s);
            }
        __syncthreads();
        const uint4* ev = (const uint4*)epi;
#pragma unroll
        for (int it = 0; it < 8; it++) {
            int idx = tid + it * 256;         // 2048 uint4
            int r = idx >> 4, c = idx & 15;
            *(uint4*)(g_c1 + ((size_t)(b*HWC + i0 + r)) * 1024 + j0 + c * 8) =
                ev[idx];
        }
    }
}

// ---------------------------------------------------------------------------
// Fused level-0: per-query 10x10 tap dots (fp16 HFMA2 chains, coalesced)
// staged in smem, then 81 bilinear outputs per query written to out directly.
// Grid (512); block = 16 queries; 32 groups of 8 lanes.
// ---------------------------------------------------------------------------
__global__ __launch_bounds__(256)
void w0l0_kernel(const float* __restrict__ coords,
                 float* __restrict__ out) {
    __shared__ float sW0[QT][112];           // [q][t], t = ty*10+tx (100 used)
    __shared__ float sX[QT], sY[QT];

    int bidx = blockIdx.x;
    int b    = bidx >> 8;
    int hw0  = (bidx & 255) * QT;
    int tid  = threadIdx.x;
    int sub  = tid & 7;
    int grp  = tid >> 3;
    int q    = grp >> 1;
    int half = grp & 1;
    int n    = b * HWC + hw0 + q;

    if (tid < QT) {
        sX[tid] = coords[(b*2 + 0) * HWC + hw0 + tid];
        sY[tid] = coords[(b*2 + 1) * HWC + hw0 + tid];
    }

    // f1 chunks {u*8+sub} as half2 (coalesced 128B per group per iteration)
    __half2 rh1[16];
    {
        const uint4* p = (const uint4*)(g_f1h + (size_t)n * CC);
#pragma unroll
        for (int u = 0; u < 4; u++) {
            uint4 h8 = p[u * 8 + sub];
            rh1[u*4+0] = *(const __half2*)&h8.x;
            rh1[u*4+1] = *(const __half2*)&h8.y;
            rh1[u*4+2] = *(const __half2*)&h8.z;
            rh1[u*4+3] = *(const __half2*)&h8.w;
        }
    }
    float xq = coords[(b*2 + 0) * HWC + hw0 + q];
    float yq = coords[(b*2 + 1) * HWC + hw0 + q];
    int bx = (int)floorf(xq) - RAD;
    int by = (int)floorf(yq) - RAD;
    const __half* f2b = g_f2h + (size_t)b * HWC * CC;

#pragma unroll 5
    for (int t = half; t < 100; t += 2) {
        int ty = (t * 205) >> 11;            // /10
        int tx = t - ty * 10;
        int ix = bx + tx, iy = by + ty;
        float acc0 = 0.f, acc1 = 0.f;
        if (((unsigned)ix < 64u) & ((unsigned)iy < 64u)) {
            const uint4* p =
                (const uint4*)(f2b + ((size_t)(iy*64 + ix)) * CC);
#pragma unroll
            for (int u = 0; u < 4; u++) {
                uint4 h8 = p[u * 8 + sub];
                __half2 s = __hmul2(rh1[u*4+0], *(const __half2*)&h8.x);
                s = __hfma2(rh1[u*4+1], *(const __half2*)&h8.y, s);
                s = __hfma2(rh1[u*4+2], *(const __half2*)&h8.z, s);
                s = __hfma2(rh1[u*4+3], *(const __half2*)&h8.w, s);
                float2 f = __half22float2(s);
                acc0 += f.x;
                acc1 += f.y;
            }
        }
        float acc = acc0 + acc1;
        acc += __shfl_down_sync(0xffffffffu, acc, 4);
        acc += __shfl_down_sync(0xffffffffu, acc, 2);
        acc += __shfl_down_sync(0xffffffffu, acc, 1);
        if (sub == 0) sW0[q][t] = acc * 0.0625f;   // 1/sqrt(256)
    }
    __syncthreads();

    // l0 bilinear: 81 outputs x 16 queries
#pragma unroll
    for (int i = 0; i < 6; i++) {
        int idx = tid + i * 256;
        if (idx < 81 * QT) {
            int k  = idx >> 4;
            int qq = idx & 15;
            int cx = (int)(((unsigned)k * 57u) >> 9);        // /9
            int ry = k - cx * 9;
            float xq2 = sX[qq];
            float yq2 = sY[qq];
            float fx = xq2 - floorf(xq2);
            float fy = yq2 - floorf(yq2);
            const float* W = sW0[qq];
            float v00 = W[ ry      * 10 + cx    ];
            float v01 = W[ ry      * 10 + cx + 1];
            float v10 = W[(ry + 1) * 10 + cx    ];
            float v11 = W[(ry + 1) * 10 + cx + 1];
            float v = (1.f - fy) * ((1.f - fx) * v00 + fx * v01)
                    +        fy  * ((1.f - fx) * v10 + fx * v11);
            out[((size_t)(b * 324 + k)) * HWC + hw0 + qq] = v;
        }
    }
}

// ---------------------------------------------------------------------------
// Merged pool+sample for levels 1..3: block = 16 queries. l1 rows -> smem;
// l2/l3 pooled in smem (fp32); windows staged; 243 outputs/query.
// ---------------------------------------------------------------------------
__global__ __launch_bounds__(256)
void pool_sample_kernel(const float* __restrict__ coords,
                        float* __restrict__ out) {
    extern __shared__ __align__(16) char sm[];
    __half* sl1 = (__half*)(sm + SMP_SL1);     // [16][1024]
    float*  sl2 = (float*) (sm + SMP_SL2);     // [16][256]
    float*  sl3 = (float*) (sm + SMP_SL3);     // [16][64]
    float*  sW  = (float*) (sm + SMP_SW);      // [16][304]
    __shared__ float sX[QT], sY[QT];

    int bidx = blockIdx.x;                     // 0..511
    int b    = bidx >> 8;
    int hw0  = (bidx & 255) * QT;
    int n0   = b * HWC + hw0;
    int tid  = threadIdx.x;

    if (tid < QT) {
        sX[tid] = coords[(b*2 + 0) * HWC + hw0 + tid];
        sY[tid] = coords[(b*2 + 1) * HWC + hw0 + tid];
    }

    // load 16 l1 rows (contiguous 32 KB)
    {
        const uint4* src = (const uint4*)(g_c1 + (size_t)n0 * 1024);
        uint4* dst = (uint4*)sl1;
#pragma unroll
        for (int i = 0; i < 8; i++) dst[tid + i*256] = src[tid + i*256];
    }
    __syncthreads();

    // l2 pool (fp32): 4096 cells
#pragma unroll
    for (int i = 0; i < 16; i++) {
        int c = tid + i*256;
        int q = c >> 8, r = c & 255;
        int y = r >> 4, x = r & 15;
        const __half* base = sl1 + q*1024 + (2*y)*32 + 2*x;
        float2 p0 = __half22float2(*(const __half2*)base);
        float2 p1 = __half22float2(*(const __half2*)(base + 32));
        sl2[c] = 0.25f * (p0.x + p0.y + p1.x + p1.y);
    }
    __syncthreads();

    // l3 pool: 1024 cells
#pragma unroll
    for (int i = 0; i < 4; i++) {
        int c = tid + i*256;
        int q = c >> 6, r = c & 63;
        int y = r >> 3, x = r & 7;
        const float* base = sl2 + q*256 + (2*y)*16 + 2*x;
        sl3[c] = 0.25f * (base[0] + base[1] + base[16] + base[17]);
    }
    __syncthreads();

    // stage windows: levels 1..3, 1600 items each (16 q x 100 taps)
#pragma unroll
    for (int l = 1; l < 4; l++) {
#pragma unroll
        for (int i = 0; i < 7; i++) {
            int idx = tid + i*256;
            if (idx < 1600) {
                int q  = (int)(((unsigned)idx * 5243u) >> 19);   // /100
                int t  = idx - q * 100;
                int ty = (int)(((unsigned)t * 205u) >> 11);      // /10
                int tx = t - ty * 10;
                float sc = 1.0f / (float)(1 << l);
                float xc = sX[q] * sc, yc = sY[q] * sc;
                int ix = (int)floorf(xc) - RAD + tx;
                int iy = (int)floorf(yc) - RAD + ty;
                int Wl = 64 >> l;
                float v = 0.f;
                if (ix >= 0 && ix < Wl && iy >= 0 && iy < Wl) {
                    if      (l == 1) v = __half2float(sl1[q*1024 + iy*32 + ix]);
                    else if (l == 2) v = sl2[q*256 + iy*16 + ix];
                    else             v = sl3[q*64 + iy*8 + ix];
                }
                sW[q*304 + (l-1)*100 + t] = v;
            }
        }
    }
    __syncthreads();

    // outputs: levels 1..3, 1296 items each (81 taps x 16 q)
#pragma unroll
    for (int l = 1; l < 4; l++) {
        float sc = 1.0f / (float)(1 << l);
#pragma unroll
        for (int i = 0; i < 6; i++) {
            int idx = tid + i*256;
            if (idx < 1296) {
                int k  = idx >> 4;
                int qq = idx & 15;
                int cx = (int)(((unsigned)k * 57u) >> 9);        // /9
                int ry = k - cx * 9;
                float xq = sX[qq] * sc;
                float yq = sY[qq] * sc;
                float fx = xq - floorf(xq);
                float fy = yq - floorf(yq);
                const float* W = sW + qq*304 + (l-1)*100;
                float v00 = W[ ry      * 10 + cx    ];
                float v01 = W[ ry      * 10 + cx + 1];
                float v10 = W[(ry + 1) * 10 + cx    ];
                float v11 = W[(ry + 1) * 10 + cx + 1];
                float v = (1.f - fy) * ((1.f - fx) * v00 + fx * v01)
                        +        fy  * ((1.f - fx) * v10 + fx * v11);
                out[((size_t)(b * 324 + l * 81 + k)) * HWC + hw0 + qq] = v;
            }
        }
    }
}

// ---------------------------------------------------------------------------
extern "C" void kernel_launch(void* const* d_in, const int* in_sizes, int n_in,
                              void* d_out, int out_size) {
    const float* fmap1  = (const float*)d_in[0];
    const float* fmap2  = (const float*)d_in[1];
    const float* coords = (const float*)d_in[2];
    float* out = (float*)d_out;

    // One-time side stream + events (host-side objects; no device memory).
    static cudaStream_t s_side = nullptr;
    static cudaEvent_t  s_fork = nullptr, s_join = nullptr;
    if (s_side == nullptr) {
        cudaStreamCreateWithFlags(&s_side, cudaStreamNonBlocking);
        cudaEventCreateWithFlags(&s_fork, cudaEventDisableTiming);
        cudaEventCreateWithFlags(&s_join, cudaEventDisableTiming);
        cudaFuncSetAttribute(gemm_l1_kernel,
                             cudaFuncAttributeMaxDynamicSharedMemorySize,
                             GEMM_SMEM_BYTES);
        cudaFuncSetAttribute(pool_sample_kernel,
                             cudaFuncAttributeMaxDynamicSharedMemorySize,
                             SAMPLE_SMEM_BYTES);
    }

    dim3 tgrid(HWC / 32, CC / 32, 2*BB);
    dim3 tblk(32, 8);
    transpose_both_kernel<<<tgrid, tblk>>>(fmap1, fmap2);

    // Fork: fused w0+l0 on side stream (needs only transposed features,
    // writes the l0 quarter of out). Main stream: pool_f2 + gemm_l1.
    cudaEventRecord(s_fork, 0);
    cudaStreamWaitEvent(s_side, s_fork, 0);

    w0l0_kernel<<<NQ / QT, 256, 0, s_side>>>(coords, out);
    cudaEventRecord(s_join, s_side);

    pool_f2_kernel<<<(BB*1024*(CC/2) + 255) / 256, 256>>>();
    dim3 ggrid(1024 / TN, HWC / TM, BB);  // (8, 32, 2)
    gemm_l1_kernel<<<ggrid, 256, GEMM_SMEM_BYTES>>>();

    // Join: ensure side-stream l0 outputs complete before capture end.
    cudaStreamWaitEvent(0, s_join, 0);
    pool_sample_kernel<<<NQ / QT, 256, SAMPLE_SMEM_BYTES>>>(coords, out);
}